// round 6
// baseline (speedup 1.0000x reference)
#include <cuda_runtime.h>
#include <cuda_bf16.h>
#include <math.h>
#include <stdint.h>

#define NNODES 50000
#define NEDGES 800000
#define NTOT   (NNODES + NEDGES)
#define FEAT 128
#define NHEADS 8

// ---- device scratch (no runtime allocation allowed) ----
__device__ int   g_count[NNODES];
__device__ int   g_rowptr[NNODES + 1];
__device__ int   g_rank[NTOT];
__device__ int   g_ssrc[NTOT];
__device__ float g_h[NNODES * FEAT];
__device__ float g_x2[NNODES * FEAT];
__device__ float g_as[NNODES * NHEADS];
__device__ float g_ad[NNODES * NHEADS];
// W split to bf16 hi/lo and transposed to [n][k] (B^T row-major), per layer
__device__ __nv_bfloat16 g_wt_hi[2][128 * 128];
__device__ __nv_bfloat16 g_wt_lo[2][128 * 128];

// ================= CSR build ===============================================
__global__ void k_hist(const int* __restrict__ dst, int e, int n) {
    int i = blockIdx.x * blockDim.x + threadIdx.x;
    int tot = e + n;
    if (i >= tot) return;
    int d = (i < e) ? dst[i] : (i - e);
    g_rank[i] = atomicAdd(&g_count[d], 1);
}

__global__ void k_scan(int n) {
    __shared__ int wsum[32];
    __shared__ int carry;
    int tid = threadIdx.x, lane = tid & 31, wid = tid >> 5;
    if (tid == 0) carry = 0;
    __syncthreads();
    for (int base = 0; base < n; base += 1024) {
        int i = base + tid;
        int v = (i < n) ? g_count[i] : 0;
        int x = v;
        #pragma unroll
        for (int off = 1; off < 32; off <<= 1) {
            int t = __shfl_up_sync(0xffffffffu, x, off);
            if (lane >= off) x += t;
        }
        if (lane == 31) wsum[wid] = x;
        __syncthreads();
        if (wid == 0) {
            int w = wsum[lane];
            #pragma unroll
            for (int off = 1; off < 32; off <<= 1) {
                int t = __shfl_up_sync(0xffffffffu, w, off);
                if (lane >= off) w += t;
            }
            wsum[lane] = w;
        }
        __syncthreads();
        int prefix = (wid > 0) ? wsum[wid - 1] : 0;
        int excl = carry + prefix + x - v;
        if (i < n) g_rowptr[i] = excl;
        __syncthreads();
        if (tid == 0) carry += wsum[31];
        __syncthreads();
    }
    if (threadIdx.x == 0) g_rowptr[n] = carry;
}

__global__ void k_scatter(const int* __restrict__ src, const int* __restrict__ dst,
                          int e, int n) {
    int i = blockIdx.x * blockDim.x + threadIdx.x;
    int tot = e + n;
    if (i >= tot) return;
    int s, d;
    if (i < e) { s = src[i]; d = dst[i]; }
    else       { s = i - e;  d = i - e;  }
    g_ssrc[g_rowptr[d] + g_rank[i]] = s;
}

// ================= W prep: split + transpose (once) ========================
__global__ void k_prepw(const float* __restrict__ W, int layer) {
    int i = blockIdx.x * blockDim.x + threadIdx.x;
    if (i >= 128 * 128) return;
    int k = i >> 7, nn = i & 127;          // W[k][nn]
    float w = W[i];
    __nv_bfloat16 hi = __float2bfloat16(w);
    __nv_bfloat16 lo = __float2bfloat16(w - __bfloat162float(hi));
    g_wt_hi[layer][nn * 128 + k] = hi;     // [n][k]
    g_wt_lo[layer][nn * 128 + k] = lo;
}

// ================= mma.sync bf16-split GEMM + fused alpha =================
// H[64-row tile, 128] = X @ W.  128 threads (4 warps), warp owns 16 rows.
// 3-pass split: hi*hi + hi*lo + lo*hi (error ~1e-5), fp32 accumulators.
#define SXW 136                    // bf16 stride (=68 words -> bank-stride 4)
#define SM_XH 0
#define SM_XL (64 * SXW * 2)
#define SM_WH (2 * 64 * SXW * 2)
#define SM_WL (SM_WH + 128 * SXW * 2)
#define GEMM_SMEM (SM_WL + 128 * SXW * 2)   // 104448 B

__device__ __forceinline__ void mma16816(float* d, uint32_t a0, uint32_t a1,
                                         uint32_t a2, uint32_t a3,
                                         uint32_t b0, uint32_t b1) {
    asm volatile(
        "mma.sync.aligned.m16n8k16.row.col.f32.bf16.bf16.f32 "
        "{%0,%1,%2,%3}, {%4,%5,%6,%7}, {%8,%9}, {%0,%1,%2,%3};"
        : "+f"(d[0]), "+f"(d[1]), "+f"(d[2]), "+f"(d[3])
        : "r"(a0), "r"(a1), "r"(a2), "r"(a3), "r"(b0), "r"(b1));
}

__global__ void __launch_bounds__(128, 2)
k_gemm_hmma(const float* __restrict__ X,
            const __nv_bfloat16* __restrict__ wth, const __nv_bfloat16* __restrict__ wtl,
            float* __restrict__ H,
            const float* __restrict__ asrc, const float* __restrict__ adst, int n) {
    extern __shared__ unsigned char sm[];
    __nv_bfloat16* sXh = (__nv_bfloat16*)(sm + SM_XH);
    __nv_bfloat16* sXl = (__nv_bfloat16*)(sm + SM_XL);
    __nv_bfloat16* sWh = (__nv_bfloat16*)(sm + SM_WH);
    __nv_bfloat16* sWl = (__nv_bfloat16*)(sm + SM_WL);
    __shared__ float sA[128], sB[128];

    int tid = threadIdx.x, lane = tid & 31, warp = tid >> 5;
    if (tid < 128) { sA[tid] = asrc[tid]; sB[tid] = adst[tid]; }

    // W tiles: copy prebuilt [n][k] bf16 into padded smem (16B chunks)
    for (int i = tid; i < 128 * 16; i += 128) {
        int r = i >> 4, c = i & 15;                   // c: 16B chunk (8 bf16)
        *(uint4*)&sWh[r * SXW + c * 8] = ((const uint4*)wth)[r * 16 + c];
        *(uint4*)&sWl[r * SXW + c * 8] = ((const uint4*)wtl)[r * 16 + c];
    }
    // X tile: load fp32, split to bf16 hi/lo
    int rbase = blockIdx.x * 64;
    for (int i = tid * 4; i < 64 * 128; i += 512) {
        int r = i >> 7, k = i & 127;
        float4 v = make_float4(0.f, 0.f, 0.f, 0.f);
        int gr = rbase + r;
        if (gr < n) v = *(const float4*)&X[(size_t)gr * FEAT + k];
        __nv_bfloat16 h0 = __float2bfloat16(v.x), h1 = __float2bfloat16(v.y);
        __nv_bfloat16 h2 = __float2bfloat16(v.z), h3 = __float2bfloat16(v.w);
        __nv_bfloat16 l0 = __float2bfloat16(v.x - __bfloat162float(h0));
        __nv_bfloat16 l1 = __float2bfloat16(v.y - __bfloat162float(h1));
        __nv_bfloat16 l2 = __float2bfloat16(v.z - __bfloat162float(h2));
        __nv_bfloat16 l3 = __float2bfloat16(v.w - __bfloat162float(h3));
        __nv_bfloat16* ph = &sXh[r * SXW + k];
        __nv_bfloat16* pl = &sXl[r * SXW + k];
        ph[0] = h0; ph[1] = h1; ph[2] = h2; ph[3] = h3;
        pl[0] = l0; pl[1] = l1; pl[2] = l2; pl[3] = l3;
    }
    __syncthreads();

    int g  = lane >> 2;          // 0..7
    int qk = (lane & 3) * 2;     // k offset within fragment
    int rowA = warp * 16 + g;

    float d[16][4];
    #pragma unroll
    for (int t = 0; t < 16; t++)
        #pragma unroll
        for (int j = 0; j < 4; j++) d[t][j] = 0.f;

    const __nv_bfloat16* pxh0 = &sXh[rowA * SXW];
    const __nv_bfloat16* pxh8 = &sXh[(rowA + 8) * SXW];
    const __nv_bfloat16* pxl0 = &sXl[rowA * SXW];
    const __nv_bfloat16* pxl8 = &sXl[(rowA + 8) * SXW];

    #pragma unroll
    for (int ks = 0; ks < 8; ks++) {
        int k0 = ks * 16 + qk;
        uint32_t ah0 = *(const uint32_t*)&pxh0[k0];
        uint32_t ah1 = *(const uint32_t*)&pxh8[k0];
        uint32_t ah2 = *(const uint32_t*)&pxh0[k0 + 8];
        uint32_t ah3 = *(const uint32_t*)&pxh8[k0 + 8];
        uint32_t al0 = *(const uint32_t*)&pxl0[k0];
        uint32_t al1 = *(const uint32_t*)&pxl8[k0];
        uint32_t al2 = *(const uint32_t*)&pxl0[k0 + 8];
        uint32_t al3 = *(const uint32_t*)&pxl8[k0 + 8];
        #pragma unroll
        for (int nt = 0; nt < 16; nt++) {
            const __nv_bfloat16* pwh = &sWh[(nt * 8 + g) * SXW + k0];
            const __nv_bfloat16* pwl = &sWl[(nt * 8 + g) * SXW + k0];
            uint32_t bh0 = *(const uint32_t*)&pwh[0];
            uint32_t bh1 = *(const uint32_t*)&pwh[8];
            uint32_t bl0 = *(const uint32_t*)&pwl[0];
            uint32_t bl1 = *(const uint32_t*)&pwl[8];
            mma16816(d[nt], ah0, ah1, ah2, ah3, bh0, bh1);
            mma16816(d[nt], ah0, ah1, ah2, ah3, bl0, bl1);
            mma16816(d[nt], al0, al1, al2, al3, bh0, bh1);
        }
    }

    // ---- store H + fused alpha dot-products ----
    int r0g = rbase + warp * 16 + g;
    int r1g = r0g + 8;
    bool v0 = r0g < n, v1 = r1g < n;

    #pragma unroll
    for (int nt = 0; nt < 16; nt++) {
        int n0 = nt * 8 + qk;
        if (v0) *(float2*)&H[(size_t)r0g * FEAT + n0] = make_float2(d[nt][0], d[nt][1]);
        if (v1) *(float2*)&H[(size_t)r1g * FEAT + n0] = make_float2(d[nt][2], d[nt][3]);
    }

    #pragma unroll
    for (int h = 0; h < NHEADS; h++) {
        int nA = 2 * h * 8 + qk, nB = (2 * h + 1) * 8 + qk;
        float aA0 = sA[nA], aA1 = sA[nA + 1], aB0 = sA[nB], aB1 = sA[nB + 1];
        float dA0 = sB[nA], dA1 = sB[nA + 1], dB0 = sB[nB], dB1 = sB[nB + 1];
        float ps0 = d[2*h][0] * aA0 + d[2*h][1] * aA1 + d[2*h+1][0] * aB0 + d[2*h+1][1] * aB1;
        float pd0 = d[2*h][0] * dA0 + d[2*h][1] * dA1 + d[2*h+1][0] * dB0 + d[2*h+1][1] * dB1;
        float ps1 = d[2*h][2] * aA0 + d[2*h][3] * aA1 + d[2*h+1][2] * aB0 + d[2*h+1][3] * aB1;
        float pd1 = d[2*h][2] * dA0 + d[2*h][3] * dA1 + d[2*h+1][2] * dB0 + d[2*h+1][3] * dB1;
        ps0 += __shfl_xor_sync(0xffffffffu, ps0, 1);
        ps0 += __shfl_xor_sync(0xffffffffu, ps0, 2);
        pd0 += __shfl_xor_sync(0xffffffffu, pd0, 1);
        pd0 += __shfl_xor_sync(0xffffffffu, pd0, 2);
        ps1 += __shfl_xor_sync(0xffffffffu, ps1, 1);
        ps1 += __shfl_xor_sync(0xffffffffu, ps1, 2);
        pd1 += __shfl_xor_sync(0xffffffffu, pd1, 1);
        pd1 += __shfl_xor_sync(0xffffffffu, pd1, 2);
        if ((lane & 3) == 0) {
            if (v0) { g_as[r0g * NHEADS + h] = ps0; g_ad[r0g * NHEADS + h] = pd0; }
            if (v1) { g_as[r1g * NHEADS + h] = ps1; g_ad[r1g * NHEADS + h] = pd1; }
        }
    }
}

// ================= aggregation (unchanged) ================================
__global__ void k_aggregate(const float* __restrict__ H, const float* __restrict__ bias,
                            float* __restrict__ out, int n) {
    int gw = (blockIdx.x * blockDim.x + threadIdx.x) >> 5;
    int lane = threadIdx.x & 31;
    if (gw >= n) return;
    int beg = g_rowptr[gw], end = g_rowptr[gw + 1];

    int head = lane >> 2;
    float adh = __ldg(&g_ad[gw * NHEADS + head]);

    float a0 = 0.f, a1 = 0.f, a2 = 0.f, a3 = 0.f, ssum = 0.f;

    int slot = lane & 3;
    int myj = beg + slot;
    int sj = (myj < end) ? __ldg(&g_ssrc[myj]) : 0;

    int j = beg;
    int jfull = beg + ((end - beg) & ~3);
    for (; j < jfull; j += 4) {
        int nx = j + 4 + slot;
        int sj_next = (nx < end) ? __ldg(&g_ssrc[nx]) : 0;
        #pragma unroll
        for (int t = 0; t < 4; t++) {
            int s = __shfl_sync(0xffffffffu, sj, t);
            float e = __ldg(&g_as[s * NHEADS + head]) + adh;
            e = (e > 0.f) ? e : 0.2f * e;
            float w = __expf(e);
            float4 hv = *(const float4*)&H[(size_t)s * FEAT + lane * 4];
            a0 += w * hv.x; a1 += w * hv.y; a2 += w * hv.z; a3 += w * hv.w;
            ssum += w;
        }
        sj = sj_next;
    }
    int rem = end - j;
    for (int t = 0; t < rem; t++) {
        int s = __shfl_sync(0xffffffffu, sj, t);
        float e = __ldg(&g_as[s * NHEADS + head]) + adh;
        e = (e > 0.f) ? e : 0.2f * e;
        float w = __expf(e);
        float4 hv = *(const float4*)&H[(size_t)s * FEAT + lane * 4];
        a0 += w * hv.x; a1 += w * hv.y; a2 += w * hv.z; a3 += w * hv.w;
        ssum += w;
    }

    float inv = 1.0f / (ssum + 1e-16f);
    float4 b = *(const float4*)&bias[lane * 4];
    float o0 = a0 * inv + b.x;
    float o1 = a1 * inv + b.y;
    float o2 = a2 * inv + b.z;
    float o3 = a3 * inv + b.w;
    o0 = (o0 > 0.f) ? o0 : (__expf(o0) - 1.f);
    o1 = (o1 > 0.f) ? o1 : (__expf(o1) - 1.f);
    o2 = (o2 > 0.f) ? o2 : (__expf(o2) - 1.f);
    o3 = (o3 > 0.f) ? o3 : (__expf(o3) - 1.f);
    *(float4*)&out[(size_t)gw * FEAT + lane * 4] = make_float4(o0, o1, o2, o3);
}

// ==========================================================================
extern "C" void kernel_launch(void* const* d_in, const int* in_sizes, int n_in,
                              void* d_out, int out_size) {
    const float* x   = (const float*)d_in[0];
    const int*   ei  = (const int*)  d_in[1];
    const float* W1  = (const float*)d_in[2];
    const float* as1 = (const float*)d_in[3];
    const float* ad1 = (const float*)d_in[4];
    const float* b1  = (const float*)d_in[5];
    const float* W2  = (const float*)d_in[6];
    const float* as2 = (const float*)d_in[7];
    const float* ad2 = (const float*)d_in[8];
    const float* b2  = (const float*)d_in[9];
    float* out = (float*)d_out;

    int n = in_sizes[0] / FEAT;   // 50000
    int e = in_sizes[1] / 2;      // 800000
    const int* src = ei;
    const int* dst = ei + e;
    int tot = e + n;

    float *p_h, *p_x2;
    int   *p_count;
    __nv_bfloat16 *p_wth, *p_wtl;
    cudaGetSymbolAddress((void**)&p_h,  g_h);
    cudaGetSymbolAddress((void**)&p_x2, g_x2);
    cudaGetSymbolAddress((void**)&p_count, g_count);
    cudaGetSymbolAddress((void**)&p_wth, g_wt_hi);
    cudaGetSymbolAddress((void**)&p_wtl, g_wt_lo);
    cudaFuncSetAttribute(k_gemm_hmma, cudaFuncAttributeMaxDynamicSharedMemorySize, GEMM_SMEM);

    int gtiles = (n + 63) / 64;

    // W prep (both layers) + CSR build
    k_prepw<<<64, 256>>>(W1, 0);
    k_prepw<<<64, 256>>>(W2, 1);
    cudaMemsetAsync(p_count, 0, n * sizeof(int));
    k_hist   <<<(tot + 255) / 256, 256>>>(dst, e, n);
    k_scan   <<<1, 1024>>>(n);
    k_scatter<<<(tot + 255) / 256, 256>>>(src, dst, e, n);

    // layer 1
    k_gemm_hmma<<<gtiles, 128, GEMM_SMEM>>>(x, p_wth, p_wtl, p_h, as1, ad1, n);
    k_aggregate<<<(n + 7) / 8, 256>>>(p_h, b1, p_x2, n);

    // layer 2
    k_gemm_hmma<<<gtiles, 128, GEMM_SMEM>>>(p_x2, p_wth + 128 * 128, p_wtl + 128 * 128,
                                            p_h, as2, ad2, n);
    k_aggregate<<<(n + 7) / 8, 256>>>(p_h, b2, out, n);
}

// round 8
// speedup vs baseline: 1.1788x; 1.1788x over previous
#include <cuda_runtime.h>
#include <cuda_bf16.h>
#include <cuda_fp16.h>
#include <math.h>
#include <stdint.h>

#define NNODES 50000
#define NEDGES 800000
#define NTOT   (NNODES + NEDGES)
#define FEAT 128
#define NHEADS 8
#define SCANB 64          // max scan blocks (50000/1024 -> 49)

// ---- device scratch (no runtime allocation allowed) ----
__device__ int   g_count[NNODES];
__device__ int   g_rowptr[NNODES + 1];
__device__ int   g_rank[NTOT];
__device__ int   g_ssrc[NTOT];
__device__ int   g_bsum[SCANB];
__device__ int   g_boff[SCANB];
__device__ __half g_hf[NNODES * FEAT];    // fp16 H (gather source for aggregate)
__device__ float g_x2[NNODES * FEAT];     // layer-1 output (fp32)
__device__ float g_as[NNODES * NHEADS];
__device__ float g_ad[NNODES * NHEADS];
// W split to bf16 hi/lo and transposed to [n][k] (B^T row-major), per layer
__device__ __nv_bfloat16 g_wt_hi[2][128 * 128];
__device__ __nv_bfloat16 g_wt_lo[2][128 * 128];

// ================= CSR build ===============================================
__global__ void k_hist(const int* __restrict__ dst, int e, int n) {
    int i = blockIdx.x * blockDim.x + threadIdx.x;
    int tot = e + n;
    if (i >= tot) return;
    int d = (i < e) ? dst[i] : (i - e);
    g_rank[i] = atomicAdd(&g_count[d], 1);
}

// stage 1: per-block (1024 elems) sums
__global__ void k_bsum(int n) {
    __shared__ int ws[32];
    int tid = threadIdx.x, lane = tid & 31, wid = tid >> 5;
    int i = blockIdx.x * 1024 + tid;
    int v = (i < n) ? g_count[i] : 0;
    #pragma unroll
    for (int off = 16; off >= 1; off >>= 1)
        v += __shfl_xor_sync(0xffffffffu, v, off);
    if (lane == 0) ws[wid] = v;
    __syncthreads();
    if (wid == 0) {
        int s = ws[lane];
        #pragma unroll
        for (int off = 16; off >= 1; off >>= 1)
            s += __shfl_xor_sync(0xffffffffu, s, off);
        if (lane == 0) g_bsum[blockIdx.x] = s;
    }
}

// stage 2: scan of block sums (<=64), one block of 64 threads
__global__ void k_scanb(int nb, int n) {
    int t = threadIdx.x;
    __shared__ int w0tot;
    int v = (t < nb) ? g_bsum[t] : 0;
    int x = v;
    #pragma unroll
    for (int off = 1; off < 32; off <<= 1) {
        int u = __shfl_up_sync(0xffffffffu, x, off);
        if ((t & 31) >= off) x += u;
    }
    if (t == 31) w0tot = x;
    __syncthreads();
    if (t >= 32) x += w0tot;
    g_boff[t] = x - v;                        // exclusive
    if (t == nb - 1) g_rowptr[n] = x;         // grand total
}

// stage 3: per-block scan + block offset -> rowptr
__global__ void k_scanf(int n) {
    __shared__ int ws[32];
    int tid = threadIdx.x, lane = tid & 31, wid = tid >> 5;
    int i = blockIdx.x * 1024 + tid;
    int v = (i < n) ? g_count[i] : 0;
    int x = v;
    #pragma unroll
    for (int off = 1; off < 32; off <<= 1) {
        int u = __shfl_up_sync(0xffffffffu, x, off);
        if (lane >= off) x += u;
    }
    if (lane == 31) ws[wid] = x;
    __syncthreads();
    if (wid == 0) {
        int w = ws[lane];
        #pragma unroll
        for (int off = 1; off < 32; off <<= 1) {
            int u = __shfl_up_sync(0xffffffffu, w, off);
            if (lane >= off) w += u;
        }
        ws[lane] = w;
    }
    __syncthreads();
    int prefix = (wid > 0) ? ws[wid - 1] : 0;
    if (i < n) g_rowptr[i] = g_boff[blockIdx.x] + prefix + x - v;
}

__global__ void k_scatter(const int* __restrict__ src, const int* __restrict__ dst,
                          int e, int n) {
    int i = blockIdx.x * blockDim.x + threadIdx.x;
    int tot = e + n;
    if (i >= tot) return;
    int s, d;
    if (i < e) { s = src[i]; d = dst[i]; }
    else       { s = i - e;  d = i - e;  }
    g_ssrc[g_rowptr[d] + g_rank[i]] = s;
}

// ================= W prep: split + transpose (once) ========================
__global__ void k_prepw(const float* __restrict__ W, int layer) {
    int i = blockIdx.x * blockDim.x + threadIdx.x;
    if (i >= 128 * 128) return;
    int k = i >> 7, nn = i & 127;          // W[k][nn]
    float w = W[i];
    __nv_bfloat16 hi = __float2bfloat16(w);
    __nv_bfloat16 lo = __float2bfloat16(w - __bfloat162float(hi));
    g_wt_hi[layer][nn * 128 + k] = hi;     // [n][k]
    g_wt_lo[layer][nn * 128 + k] = lo;
}

// ================= mma.sync bf16-split GEMM + fused alpha =================
// Hf16[64-row tile, 128] = X @ W.  128 threads (4 warps), warp owns 16 rows.
// 3-pass split: hi*hi + hi*lo + lo*hi (error ~1e-5), fp32 accumulators.
#define SXW 136                    // bf16 stride (=68 words -> bank-stride 4)
#define SM_XH 0
#define SM_XL (64 * SXW * 2)
#define SM_WH (2 * 64 * SXW * 2)
#define SM_WL (SM_WH + 128 * SXW * 2)
#define GEMM_SMEM (SM_WL + 128 * SXW * 2)   // 104448 B

__device__ __forceinline__ void mma16816(float* d, uint32_t a0, uint32_t a1,
                                         uint32_t a2, uint32_t a3,
                                         uint32_t b0, uint32_t b1) {
    asm volatile(
        "mma.sync.aligned.m16n8k16.row.col.f32.bf16.bf16.f32 "
        "{%0,%1,%2,%3}, {%4,%5,%6,%7}, {%8,%9}, {%0,%1,%2,%3};"
        : "+f"(d[0]), "+f"(d[1]), "+f"(d[2]), "+f"(d[3])
        : "r"(a0), "r"(a1), "r"(a2), "r"(a3), "r"(b0), "r"(b1));
}

__global__ void __launch_bounds__(128, 2)
k_gemm_hmma(const float* __restrict__ X,
            const __nv_bfloat16* __restrict__ wth, const __nv_bfloat16* __restrict__ wtl,
            __half* __restrict__ Hf,
            const float* __restrict__ asrc, const float* __restrict__ adst, int n) {
    extern __shared__ unsigned char sm[];
    __nv_bfloat16* sXh = (__nv_bfloat16*)(sm + SM_XH);
    __nv_bfloat16* sXl = (__nv_bfloat16*)(sm + SM_XL);
    __nv_bfloat16* sWh = (__nv_bfloat16*)(sm + SM_WH);
    __nv_bfloat16* sWl = (__nv_bfloat16*)(sm + SM_WL);
    __shared__ float sA[128], sB[128];

    int tid = threadIdx.x, lane = tid & 31, warp = tid >> 5;
    if (tid < 128) { sA[tid] = asrc[tid]; sB[tid] = adst[tid]; }

    for (int i = tid; i < 128 * 16; i += 128) {
        int r = i >> 4, c = i & 15;                   // c: 16B chunk (8 bf16)
        *(uint4*)&sWh[r * SXW + c * 8] = ((const uint4*)wth)[r * 16 + c];
        *(uint4*)&sWl[r * SXW + c * 8] = ((const uint4*)wtl)[r * 16 + c];
    }
    int rbase = blockIdx.x * 64;
    for (int i = tid * 4; i < 64 * 128; i += 512) {
        int r = i >> 7, k = i & 127;
        float4 v = make_float4(0.f, 0.f, 0.f, 0.f);
        int gr = rbase + r;
        if (gr < n) v = *(const float4*)&X[(size_t)gr * FEAT + k];
        __nv_bfloat16 h0 = __float2bfloat16(v.x), h1 = __float2bfloat16(v.y);
        __nv_bfloat16 h2 = __float2bfloat16(v.z), h3 = __float2bfloat16(v.w);
        __nv_bfloat16 l0 = __float2bfloat16(v.x - __bfloat162float(h0));
        __nv_bfloat16 l1 = __float2bfloat16(v.y - __bfloat162float(h1));
        __nv_bfloat16 l2 = __float2bfloat16(v.z - __bfloat162float(h2));
        __nv_bfloat16 l3 = __float2bfloat16(v.w - __bfloat162float(h3));
        __nv_bfloat16* ph = &sXh[r * SXW + k];
        __nv_bfloat16* pl = &sXl[r * SXW + k];
        ph[0] = h0; ph[1] = h1; ph[2] = h2; ph[3] = h3;
        pl[0] = l0; pl[1] = l1; pl[2] = l2; pl[3] = l3;
    }
    __syncthreads();

    int g  = lane >> 2;          // 0..7
    int qk = (lane & 3) * 2;     // k offset within fragment
    int rowA = warp * 16 + g;

    float d[16][4];
    #pragma unroll
    for (int t = 0; t < 16; t++)
        #pragma unroll
        for (int j = 0; j < 4; j++) d[t][j] = 0.f;

    const __nv_bfloat16* pxh0 = &sXh[rowA * SXW];
    const __nv_bfloat16* pxh8 = &sXh[(rowA + 8) * SXW];
    const __nv_bfloat16* pxl0 = &sXl[rowA * SXW];
    const __nv_bfloat16* pxl8 = &sXl[(rowA + 8) * SXW];

    #pragma unroll
    for (int ks = 0; ks < 8; ks++) {
        int k0 = ks * 16 + qk;
        uint32_t ah0 = *(const uint32_t*)&pxh0[k0];
        uint32_t ah1 = *(const uint32_t*)&pxh8[k0];
        uint32_t ah2 = *(const uint32_t*)&pxh0[k0 + 8];
        uint32_t ah3 = *(const uint32_t*)&pxh8[k0 + 8];
        uint32_t al0 = *(const uint32_t*)&pxl0[k0];
        uint32_t al1 = *(const uint32_t*)&pxl8[k0];
        uint32_t al2 = *(const uint32_t*)&pxl0[k0 + 8];
        uint32_t al3 = *(const uint32_t*)&pxl8[k0 + 8];
        #pragma unroll
        for (int nt = 0; nt < 16; nt++) {
            const __nv_bfloat16* pwh = &sWh[(nt * 8 + g) * SXW + k0];
            const __nv_bfloat16* pwl = &sWl[(nt * 8 + g) * SXW + k0];
            uint32_t bh0 = *(const uint32_t*)&pwh[0];
            uint32_t bh1 = *(const uint32_t*)&pwh[8];
            uint32_t bl0 = *(const uint32_t*)&pwl[0];
            uint32_t bl1 = *(const uint32_t*)&pwl[8];
            mma16816(d[nt], ah0, ah1, ah2, ah3, bh0, bh1);
            mma16816(d[nt], ah0, ah1, ah2, ah3, bl0, bl1);
            mma16816(d[nt], al0, al1, al2, al3, bh0, bh1);
        }
    }

    // ---- store H (fp16) + fused alpha dot-products (fp32) ----
    int r0g = rbase + warp * 16 + g;
    int r1g = r0g + 8;
    bool v0 = r0g < n, v1 = r1g < n;

    #pragma unroll
    for (int nt = 0; nt < 16; nt++) {
        int n0 = nt * 8 + qk;
        if (v0) *(__half2*)&Hf[(size_t)r0g * FEAT + n0] = __floats2half2_rn(d[nt][0], d[nt][1]);
        if (v1) *(__half2*)&Hf[(size_t)r1g * FEAT + n0] = __floats2half2_rn(d[nt][2], d[nt][3]);
    }

    #pragma unroll
    for (int h = 0; h < NHEADS; h++) {
        int nA = 2 * h * 8 + qk, nB = (2 * h + 1) * 8 + qk;
        float aA0 = sA[nA], aA1 = sA[nA + 1], aB0 = sA[nB], aB1 = sA[nB + 1];
        float dA0 = sB[nA], dA1 = sB[nA + 1], dB0 = sB[nB], dB1 = sB[nB + 1];
        float ps0 = d[2*h][0] * aA0 + d[2*h][1] * aA1 + d[2*h+1][0] * aB0 + d[2*h+1][1] * aB1;
        float pd0 = d[2*h][0] * dA0 + d[2*h][1] * dA1 + d[2*h+1][0] * dB0 + d[2*h+1][1] * dB1;
        float ps1 = d[2*h][2] * aA0 + d[2*h][3] * aA1 + d[2*h+1][2] * aB0 + d[2*h+1][3] * aB1;
        float pd1 = d[2*h][2] * dA0 + d[2*h][3] * dA1 + d[2*h+1][2] * dB0 + d[2*h+1][3] * dB1;
        ps0 += __shfl_xor_sync(0xffffffffu, ps0, 1);
        ps0 += __shfl_xor_sync(0xffffffffu, ps0, 2);
        pd0 += __shfl_xor_sync(0xffffffffu, pd0, 1);
        pd0 += __shfl_xor_sync(0xffffffffu, pd0, 2);
        ps1 += __shfl_xor_sync(0xffffffffu, ps1, 1);
        ps1 += __shfl_xor_sync(0xffffffffu, ps1, 2);
        pd1 += __shfl_xor_sync(0xffffffffu, pd1, 1);
        pd1 += __shfl_xor_sync(0xffffffffu, pd1, 2);
        if ((lane & 3) == 0) {
            if (v0) { g_as[r0g * NHEADS + h] = ps0; g_ad[r0g * NHEADS + h] = pd0; }
            if (v1) { g_as[r1g * NHEADS + h] = ps1; g_ad[r1g * NHEADS + h] = pd1; }
        }
    }
}

// ================= aggregation (fp16 H gather, fp32 math) =================
__global__ void k_aggregate(const __half* __restrict__ Hf, const float* __restrict__ bias,
                            float* __restrict__ out, int n) {
    int gw = (blockIdx.x * blockDim.x + threadIdx.x) >> 5;
    int lane = threadIdx.x & 31;
    if (gw >= n) return;
    int beg = g_rowptr[gw], end = g_rowptr[gw + 1];

    int head = lane >> 2;
    float adh = __ldg(&g_ad[gw * NHEADS + head]);

    float a0 = 0.f, a1 = 0.f, a2 = 0.f, a3 = 0.f, ssum = 0.f;

    int slot = lane & 3;
    int myj = beg + slot;
    int sj = (myj < end) ? __ldg(&g_ssrc[myj]) : 0;

    int j = beg;
    int jfull = beg + ((end - beg) & ~3);
    for (; j < jfull; j += 4) {
        int nx = j + 4 + slot;
        int sj_next = (nx < end) ? __ldg(&g_ssrc[nx]) : 0;
        #pragma unroll
        for (int t = 0; t < 4; t++) {
            int s = __shfl_sync(0xffffffffu, sj, t);
            float e = __ldg(&g_as[s * NHEADS + head]) + adh;
            e = (e > 0.f) ? e : 0.2f * e;
            float w = __expf(e);
            uint2 hv = *(const uint2*)&Hf[(size_t)s * FEAT + lane * 4];
            float2 f0 = __half22float2(*(__half2*)&hv.x);
            float2 f1 = __half22float2(*(__half2*)&hv.y);
            a0 += w * f0.x; a1 += w * f0.y; a2 += w * f1.x; a3 += w * f1.y;
            ssum += w;
        }
        sj = sj_next;
    }
    int rem = end - j;
    for (int t = 0; t < rem; t++) {
        int s = __shfl_sync(0xffffffffu, sj, t);
        float e = __ldg(&g_as[s * NHEADS + head]) + adh;
        e = (e > 0.f) ? e : 0.2f * e;
        float w = __expf(e);
        uint2 hv = *(const uint2*)&Hf[(size_t)s * FEAT + lane * 4];
        float2 f0 = __half22float2(*(__half2*)&hv.x);
        float2 f1 = __half22float2(*(__half2*)&hv.y);
        a0 += w * f0.x; a1 += w * f0.y; a2 += w * f1.x; a3 += w * f1.y;
        ssum += w;
    }

    float inv = 1.0f / (ssum + 1e-16f);
    float4 b = *(const float4*)&bias[lane * 4];
    float o0 = a0 * inv + b.x;
    float o1 = a1 * inv + b.y;
    float o2 = a2 * inv + b.z;
    float o3 = a3 * inv + b.w;
    o0 = (o0 > 0.f) ? o0 : (__expf(o0) - 1.f);
    o1 = (o1 > 0.f) ? o1 : (__expf(o1) - 1.f);
    o2 = (o2 > 0.f) ? o2 : (__expf(o2) - 1.f);
    o3 = (o3 > 0.f) ? o3 : (__expf(o3) - 1.f);
    *(float4*)&out[(size_t)gw * FEAT + lane * 4] = make_float4(o0, o1, o2, o3);
}

// ==========================================================================
extern "C" void kernel_launch(void* const* d_in, const int* in_sizes, int n_in,
                              void* d_out, int out_size) {
    const float* x   = (const float*)d_in[0];
    const int*   ei  = (const int*)  d_in[1];
    const float* W1  = (const float*)d_in[2];
    const float* as1 = (const float*)d_in[3];
    const float* ad1 = (const float*)d_in[4];
    const float* b1  = (const float*)d_in[5];
    const float* W2  = (const float*)d_in[6];
    const float* as2 = (const float*)d_in[7];
    const float* ad2 = (const float*)d_in[8];
    const float* b2  = (const float*)d_in[9];
    float* out = (float*)d_out;

    int n = in_sizes[0] / FEAT;   // 50000
    int e = in_sizes[1] / 2;      // 800000
    const int* src = ei;
    const int* dst = ei + e;
    int tot = e + n;
    int nb = (n + 1023) / 1024;   // scan blocks (49)

    float *p_x2;
    int   *p_count;
    __half *p_hf;
    __nv_bfloat16 *p_wth, *p_wtl;
    cudaGetSymbolAddress((void**)&p_hf, g_hf);
    cudaGetSymbolAddress((void**)&p_x2, g_x2);
    cudaGetSymbolAddress((void**)&p_count, g_count);
    cudaGetSymbolAddress((void**)&p_wth, g_wt_hi);
    cudaGetSymbolAddress((void**)&p_wtl, g_wt_lo);
    cudaFuncSetAttribute(k_gemm_hmma, cudaFuncAttributeMaxDynamicSharedMemorySize, GEMM_SMEM);

    int gtiles = (n + 63) / 64;

    // W prep (both layers) + CSR build
    k_prepw<<<64, 256>>>(W1, 0);
    k_prepw<<<64, 256>>>(W2, 1);
    cudaMemsetAsync(p_count, 0, n * sizeof(int));
    k_hist   <<<(tot + 255) / 256, 256>>>(dst, e, n);
    k_bsum   <<<nb, 1024>>>(n);
    k_scanb  <<<1, SCANB>>>(nb, n);
    k_scanf  <<<nb, 1024>>>(n);
    k_scatter<<<(tot + 255) / 256, 256>>>(src, dst, e, n);

    // layer 1
    k_gemm_hmma<<<gtiles, 128, GEMM_SMEM>>>(x, p_wth, p_wtl, p_hf, as1, ad1, n);
    k_aggregate<<<(n + 7) / 8, 256>>>(p_hf, b1, p_x2, n);

    // layer 2
    k_gemm_hmma<<<gtiles, 128, GEMM_SMEM>>>(p_x2, p_wth + 128 * 128, p_wtl + 128 * 128,
                                            p_hf, as2, ad2, n);
    k_aggregate<<<(n + 7) / 8, 256>>>(p_hf, b2, out, n);
}

// round 11
// speedup vs baseline: 1.2515x; 1.0617x over previous
#include <cuda_runtime.h>
#include <cuda_bf16.h>
#include <cuda_fp16.h>
#include <math.h>
#include <stdint.h>

#define NNODES 50000
#define NEDGES 800000
#define NTOT   (NNODES + NEDGES)
#define FEAT 128
#define NHEADS 8
#define SCANB 64          // max scan blocks (50000/1024 -> 49)

// ---- device scratch (no runtime allocation allowed) ----
__device__ int   g_count[NNODES];
__device__ int   g_rowptr[NNODES + 1];
__device__ int   g_rank[NTOT];
__device__ int   g_ssrc[NTOT];
__device__ int   g_bsum[SCANB];
__device__ __half g_hf[NNODES * FEAT];    // fp16 H (gather source for aggregate)
__device__ float g_x2[NNODES * FEAT];     // layer-1 output (fp32)
__device__ float g_as[NNODES * NHEADS];
__device__ float g_ad[NNODES * NHEADS];
// W split to bf16 hi/lo and transposed to [n][k] (B^T row-major), per layer
__device__ __nv_bfloat16 g_wt_hi[2][128 * 128];
__device__ __nv_bfloat16 g_wt_lo[2][128 * 128];

// ================= prep: W split/transpose (both layers) + zero counts =====
__global__ void k_prep(const float* __restrict__ W1, const float* __restrict__ W2, int n) {
    int i = blockIdx.x * blockDim.x + threadIdx.x;   // 65536 threads
    if (i < n) g_count[i] = 0;
    if (i < 128 * 128) {
        int k = i >> 7, nn = i & 127;          // W[k][nn]
        float w = W1[i];
        __nv_bfloat16 hi = __float2bfloat16(w);
        __nv_bfloat16 lo = __float2bfloat16(w - __bfloat162float(hi));
        g_wt_hi[0][nn * 128 + k] = hi;         // [n][k]
        g_wt_lo[0][nn * 128 + k] = lo;
        w = W2[i];
        hi = __float2bfloat16(w);
        lo = __float2bfloat16(w - __bfloat162float(hi));
        g_wt_hi[1][nn * 128 + k] = hi;
        g_wt_lo[1][nn * 128 + k] = lo;
    }
}

// ================= CSR build ===============================================
__global__ void k_hist(const int* __restrict__ dst, int e, int n) {
    int i = blockIdx.x * blockDim.x + threadIdx.x;
    int tot = e + n;
    if (i >= tot) return;
    int d = (i < e) ? dst[i] : (i - e);   // self-loops appended
    g_rank[i] = atomicAdd(&g_count[d], 1);
}

// stage 1: per-block (1024 elems) sums
__global__ void k_bsum(int n) {
    __shared__ int ws[32];
    int tid = threadIdx.x, lane = tid & 31, wid = tid >> 5;
    int i = blockIdx.x * 1024 + tid;
    int v = (i < n) ? g_count[i] : 0;
    #pragma unroll
    for (int off = 16; off >= 1; off >>= 1)
        v += __shfl_xor_sync(0xffffffffu, v, off);
    if (lane == 0) ws[wid] = v;
    __syncthreads();
    if (wid == 0) {
        int s = ws[lane];
        #pragma unroll
        for (int off = 16; off >= 1; off >>= 1)
            s += __shfl_xor_sync(0xffffffffu, s, off);
        if (lane == 0) g_bsum[blockIdx.x] = s;
    }
}

// stage 2: per-block scan; block offset computed in-kernel from g_bsum
__global__ void k_scanf(int nb, int n) {
    __shared__ int ws[32];
    __shared__ int sboff, stot;
    int tid = threadIdx.x, lane = tid & 31, wid = tid >> 5;
    if (tid == 0) { sboff = 0; stot = 0; }
    __syncthreads();
    if (tid < SCANB && tid < nb) {
        int b = g_bsum[tid];
        if (tid < blockIdx.x) atomicAdd(&sboff, b);
        atomicAdd(&stot, b);
    }
    int i = blockIdx.x * 1024 + tid;
    int v = (i < n) ? g_count[i] : 0;
    int x = v;
    #pragma unroll
    for (int off = 1; off < 32; off <<= 1) {
        int u = __shfl_up_sync(0xffffffffu, x, off);
        if (lane >= off) x += u;
    }
    if (lane == 31) ws[wid] = x;
    __syncthreads();
    if (wid == 0) {
        int w = ws[lane];
        #pragma unroll
        for (int off = 1; off < 32; off <<= 1) {
            int u = __shfl_up_sync(0xffffffffu, w, off);
            if (lane >= off) w += u;
        }
        ws[lane] = w;
    }
    __syncthreads();
    int prefix = (wid > 0) ? ws[wid - 1] : 0;
    if (i < n) g_rowptr[i] = sboff + prefix + x - v;
    if (blockIdx.x == 0 && tid == 0) g_rowptr[n] = stot;
}

__global__ void k_scatter(const int* __restrict__ src, const int* __restrict__ dst,
                          int e, int n) {
    int i = blockIdx.x * blockDim.x + threadIdx.x;
    int tot = e + n;
    if (i >= tot) return;
    int s, d;
    if (i < e) { s = src[i]; d = dst[i]; }
    else       { s = i - e;  d = i - e;  }
    g_ssrc[g_rowptr[d] + g_rank[i]] = s;
}

// ================= mma.sync bf16-split GEMM + fused alpha =================
// Hf16[128-row tile, 128] = X @ W.  256 threads (8 warps), warp owns 16 rows.
// 3-pass split: hi*hi + hi*lo + lo*hi (error ~1e-5), fp32 accumulators.
#define SXW 136                    // bf16 stride (=68 words -> bank-stride 4)
#define SM_XH 0
#define SM_XL (128 * SXW * 2)
#define SM_WH (2 * 128 * SXW * 2)
#define SM_WL (SM_WH + 128 * SXW * 2)
#define GEMM_SMEM (SM_WL + 128 * SXW * 2)   // 139264 B

__device__ __forceinline__ void mma16816(float* d, uint32_t a0, uint32_t a1,
                                         uint32_t a2, uint32_t a3,
                                         uint32_t b0, uint32_t b1) {
    asm volatile(
        "mma.sync.aligned.m16n8k16.row.col.f32.bf16.bf16.f32 "
        "{%0,%1,%2,%3}, {%4,%5,%6,%7}, {%8,%9}, {%0,%1,%2,%3};"
        : "+f"(d[0]), "+f"(d[1]), "+f"(d[2]), "+f"(d[3])
        : "r"(a0), "r"(a1), "r"(a2), "r"(a3), "r"(b0), "r"(b1));
}

__global__ void __launch_bounds__(256, 1)
k_gemm_hmma(const float* __restrict__ X,
            const __nv_bfloat16* __restrict__ wth, const __nv_bfloat16* __restrict__ wtl,
            __half* __restrict__ Hf,
            const float* __restrict__ asrc, const float* __restrict__ adst, int n) {
    extern __shared__ unsigned char sm[];
    __nv_bfloat16* sXh = (__nv_bfloat16*)(sm + SM_XH);
    __nv_bfloat16* sXl = (__nv_bfloat16*)(sm + SM_XL);
    __nv_bfloat16* sWh = (__nv_bfloat16*)(sm + SM_WH);
    __nv_bfloat16* sWl = (__nv_bfloat16*)(sm + SM_WL);
    __shared__ float sA[128], sB[128];

    int tid = threadIdx.x, lane = tid & 31, warp = tid >> 5;
    if (tid < 128) { sA[tid] = asrc[tid]; sB[tid] = adst[tid]; }

    // W tiles: copy prebuilt [n][k] bf16 into padded smem (16B chunks)
    for (int i = tid; i < 128 * 16; i += 256) {
        int r = i >> 4, c = i & 15;                   // c: 16B chunk (8 bf16)
        *(uint4*)&sWh[r * SXW + c * 8] = ((const uint4*)wth)[i];
        *(uint4*)&sWl[r * SXW + c * 8] = ((const uint4*)wtl)[i];
    }
    // X tile: load fp32, split to bf16 hi/lo
    int rbase = blockIdx.x * 128;
    for (int i = tid * 4; i < 128 * 128; i += 1024) {
        int r = i >> 7, k = i & 127;
        float4 v = make_float4(0.f, 0.f, 0.f, 0.f);
        int gr = rbase + r;
        if (gr < n) v = *(const float4*)&X[(size_t)gr * FEAT + k];
        __nv_bfloat16 h0 = __float2bfloat16(v.x), h1 = __float2bfloat16(v.y);
        __nv_bfloat16 h2 = __float2bfloat16(v.z), h3 = __float2bfloat16(v.w);
        __nv_bfloat16 l0 = __float2bfloat16(v.x - __bfloat162float(h0));
        __nv_bfloat16 l1 = __float2bfloat16(v.y - __bfloat162float(h1));
        __nv_bfloat16 l2 = __float2bfloat16(v.z - __bfloat162float(h2));
        __nv_bfloat16 l3 = __float2bfloat16(v.w - __bfloat162float(h3));
        __nv_bfloat16* ph = &sXh[r * SXW + k];
        __nv_bfloat16* pl = &sXl[r * SXW + k];
        ph[0] = h0; ph[1] = h1; ph[2] = h2; ph[3] = h3;
        pl[0] = l0; pl[1] = l1; pl[2] = l2; pl[3] = l3;
    }
    __syncthreads();

    int g  = lane >> 2;          // 0..7
    int qk = (lane & 3) * 2;     // k offset within fragment
    int rowA = warp * 16 + g;

    float d[16][4];
    #pragma unroll
    for (int t = 0; t < 16; t++)
        #pragma unroll
        for (int j = 0; j < 4; j++) d[t][j] = 0.f;

    const __nv_bfloat16* pxh0 = &sXh[rowA * SXW];
    const __nv_bfloat16* pxh8 = &sXh[(rowA + 8) * SXW];
    const __nv_bfloat16* pxl0 = &sXl[rowA * SXW];
    const __nv_bfloat16* pxl8 = &sXl[(rowA + 8) * SXW];

    #pragma unroll
    for (int ks = 0; ks < 8; ks++) {
        int k0 = ks * 16 + qk;
        uint32_t ah0 = *(const uint32_t*)&pxh0[k0];
        uint32_t ah1 = *(const uint32_t*)&pxh8[k0];
        uint32_t ah2 = *(const uint32_t*)&pxh0[k0 + 8];
        uint32_t ah3 = *(const uint32_t*)&pxh8[k0 + 8];
        uint32_t al0 = *(const uint32_t*)&pxl0[k0];
        uint32_t al1 = *(const uint32_t*)&pxl8[k0];
        uint32_t al2 = *(const uint32_t*)&pxl0[k0 + 8];
        uint32_t al3 = *(const uint32_t*)&pxl8[k0 + 8];
        #pragma unroll
        for (int nt = 0; nt < 16; nt++) {
            const __nv_bfloat16* pwh = &sWh[(nt * 8 + g) * SXW + k0];
            const __nv_bfloat16* pwl = &sWl[(nt * 8 + g) * SXW + k0];
            uint32_t bh0 = *(const uint32_t*)&pwh[0];
            uint32_t bh1 = *(const uint32_t*)&pwh[8];
            uint32_t bl0 = *(const uint32_t*)&pwl[0];
            uint32_t bl1 = *(const uint32_t*)&pwl[8];
            mma16816(d[nt], ah0, ah1, ah2, ah3, bh0, bh1);
            mma16816(d[nt], ah0, ah1, ah2, ah3, bl0, bl1);
            mma16816(d[nt], al0, al1, al2, al3, bh0, bh1);
        }
    }

    // ---- store H (fp16) + fused alpha dot-products (fp32) ----
    int r0g = rbase + warp * 16 + g;
    int r1g = r0g + 8;
    bool v0 = r0g < n, v1 = r1g < n;

    #pragma unroll
    for (int nt = 0; nt < 16; nt++) {
        int n0 = nt * 8 + qk;
        if (v0) *(__half2*)&Hf[(size_t)r0g * FEAT + n0] = __floats2half2_rn(d[nt][0], d[nt][1]);
        if (v1) *(__half2*)&Hf[(size_t)r1g * FEAT + n0] = __floats2half2_rn(d[nt][2], d[nt][3]);
    }

    #pragma unroll
    for (int h = 0; h < NHEADS; h++) {
        int nA = 2 * h * 8 + qk, nB = (2 * h + 1) * 8 + qk;
        float aA0 = sA[nA], aA1 = sA[nA + 1], aB0 = sA[nB], aB1 = sA[nB + 1];
        float dA0 = sB[nA], dA1 = sB[nA + 1], dB0 = sB[nB], dB1 = sB[nB + 1];
        float ps0 = d[2*h][0] * aA0 + d[2*h][1] * aA1 + d[2*h+1][0] * aB0 + d[2*h+1][1] * aB1;
        float pd0 = d[2*h][0] * dA0 + d[2*h][1] * dA1 + d[2*h+1][0] * dB0 + d[2*h+1][1] * dB1;
        float ps1 = d[2*h][2] * aA0 + d[2*h][3] * aA1 + d[2*h+1][2] * aB0 + d[2*h+1][3] * aB1;
        float pd1 = d[2*h][2] * dA0 + d[2*h][3] * dA1 + d[2*h+1][2] * dB0 + d[2*h+1][3] * dB1;
        ps0 += __shfl_xor_sync(0xffffffffu, ps0, 1);
        ps0 += __shfl_xor_sync(0xffffffffu, ps0, 2);
        pd0 += __shfl_xor_sync(0xffffffffu, pd0, 1);
        pd0 += __shfl_xor_sync(0xffffffffu, pd0, 2);
        ps1 += __shfl_xor_sync(0xffffffffu, ps1, 1);
        ps1 += __shfl_xor_sync(0xffffffffu, ps1, 2);
        pd1 += __shfl_xor_sync(0xffffffffu, pd1, 1);
        pd1 += __shfl_xor_sync(0xffffffffu, pd1, 2);
        if ((lane & 3) == 0) {
            if (v0) { g_as[r0g * NHEADS + h] = ps0; g_ad[r0g * NHEADS + h] = pd0; }
            if (v1) { g_as[r1g * NHEADS + h] = ps1; g_ad[r1g * NHEADS + h] = pd1; }
        }
    }
}

// ================= aggregation (fp16 H gather, fp32 math) =================
__global__ void k_aggregate(const __half* __restrict__ Hf, const float* __restrict__ bias,
                            float* __restrict__ out, int n) {
    int gw = (blockIdx.x * blockDim.x + threadIdx.x) >> 5;
    int lane = threadIdx.x & 31;
    if (gw >= n) return;
    int beg = g_rowptr[gw], end = g_rowptr[gw + 1];

    int head = lane >> 2;
    float adh = __ldg(&g_ad[gw * NHEADS + head]);

    float a0 = 0.f, a1 = 0.f, a2 = 0.f, a3 = 0.f, ssum = 0.f;

    int slot = lane & 3;
    int myj = beg + slot;
    int sj = (myj < end) ? __ldg(&g_ssrc[myj]) : 0;

    int j = beg;
    int jfull = beg + ((end - beg) & ~3);
    for (; j < jfull; j += 4) {
        int nx = j + 4 + slot;
        int sj_next = (nx < end) ? __ldg(&g_ssrc[nx]) : 0;
        #pragma unroll
        for (int t = 0; t < 4; t++) {
            int s = __shfl_sync(0xffffffffu, sj, t);
            float e = __ldg(&g_as[s * NHEADS + head]) + adh;
            e = (e > 0.f) ? e : 0.2f * e;
            float w = __expf(e);
            uint2 hv = *(const uint2*)&Hf[(size_t)s * FEAT + lane * 4];
            float2 f0 = __half22float2(*(__half2*)&hv.x);
            float2 f1 = __half22float2(*(__half2*)&hv.y);
            a0 += w * f0.x; a1 += w * f0.y; a2 += w * f1.x; a3 += w * f1.y;
            ssum += w;
        }
        sj = sj_next;
    }
    int rem = end - j;
    for (int t = 0; t < rem; t++) {
        int s = __shfl_sync(0xffffffffu, sj, t);
        float e = __ldg(&g_as[s * NHEADS + head]) + adh;
        e = (e > 0.f) ? e : 0.2f * e;
        float w = __expf(e);
        uint2 hv = *(const uint2*)&Hf[(size_t)s * FEAT + lane * 4];
        float2 f0 = __half22float2(*(__half2*)&hv.x);
        float2 f1 = __half22float2(*(__half2*)&hv.y);
        a0 += w * f0.x; a1 += w * f0.y; a2 += w * f1.x; a3 += w * f1.y;
        ssum += w;
    }

    float inv = 1.0f / (ssum + 1e-16f);
    float4 b = *(const float4*)&bias[lane * 4];
    float o0 = a0 * inv + b.x;
    float o1 = a1 * inv + b.y;
    float o2 = a2 * inv + b.z;
    float o3 = a3 * inv + b.w;
    o0 = (o0 > 0.f) ? o0 : (__expf(o0) - 1.f);
    o1 = (o1 > 0.f) ? o1 : (__expf(o1) - 1.f);
    o2 = (o2 > 0.f) ? o2 : (__expf(o2) - 1.f);
    o3 = (o3 > 0.f) ? o3 : (__expf(o3) - 1.f);
    *(float4*)&out[(size_t)gw * FEAT + lane * 4] = make_float4(o0, o1, o2, o3);
}

// ==========================================================================
extern "C" void kernel_launch(void* const* d_in, const int* in_sizes, int n_in,
                              void* d_out, int out_size) {
    const float* x   = (const float*)d_in[0];
    const int*   ei  = (const int*)  d_in[1];
    const float* W1  = (const float*)d_in[2];
    const float* as1 = (const float*)d_in[3];
    const float* ad1 = (const float*)d_in[4];
    const float* b1  = (const float*)d_in[5];
    const float* W2  = (const float*)d_in[6];
    const float* as2 = (const float*)d_in[7];
    const float* ad2 = (const float*)d_in[8];
    const float* b2  = (const float*)d_in[9];
    float* out = (float*)d_out;

    int n = in_sizes[0] / FEAT;   // 50000
    int e = in_sizes[1] / 2;      // 800000
    const int* src = ei;
    const int* dst = ei + e;
    int tot = e + n;
    int nb = (n + 1023) / 1024;   // scan blocks (49)

    float *p_x2;
    __half *p_hf;
    __nv_bfloat16 *p_wth, *p_wtl;
    cudaGetSymbolAddress((void**)&p_hf, g_hf);
    cudaGetSymbolAddress((void**)&p_x2, g_x2);
    cudaGetSymbolAddress((void**)&p_wth, g_wt_hi);
    cudaGetSymbolAddress((void**)&p_wtl, g_wt_lo);
    cudaFuncSetAttribute(k_gemm_hmma, cudaFuncAttributeMaxDynamicSharedMemorySize, GEMM_SMEM);

    int gtiles = (n + 127) / 128;

    // (1) prep: W split both layers + zero counts
    k_prep   <<<256, 256>>>(W1, W2, n);
    // (2..5) CSR build
    k_hist   <<<(tot + 255) / 256, 256>>>(dst, e, n);
    k_bsum   <<<nb, 1024>>>(n);
    k_scanf  <<<nb, 1024>>>(nb, n);
    k_scatter<<<(tot + 255) / 256, 256>>>(src, dst, e, n);

    // (6) layer-1 GEMM  <- ncu -s 5 -c 1 lands here
    k_gemm_hmma<<<gtiles, 256, GEMM_SMEM>>>(x, p_wth, p_wtl, p_hf, as1, ad1, n);
    k_aggregate<<<(n + 7) / 8, 256>>>(p_hf, b1, p_x2, n);

    // layer 2
    k_gemm_hmma<<<gtiles, 256, GEMM_SMEM>>>(p_x2, p_wth + 128 * 128, p_wtl + 128 * 128,
                                            p_hf, as2, ad2, n);
    k_aggregate<<<(n + 7) / 8, 256>>>(p_hf, b2, out, n);
}

// round 12
// speedup vs baseline: 1.3292x; 1.0621x over previous
#include <cuda_runtime.h>
#include <cuda_bf16.h>
#include <cuda_fp16.h>
#include <math.h>
#include <stdint.h>

#define NNODES 50000
#define NEDGES 800000
#define NTOT   (NNODES + NEDGES)
#define FEAT 128
#define NHEADS 8
#define SCANB 64          // max scan blocks (50000/1024 -> 49)

// ---- device scratch (no runtime allocation allowed) ----
__device__ int   g_count[NNODES];
__device__ int   g_rowptr[NNODES + 1];
__device__ int   g_rank[NTOT];
__device__ int   g_ssrc[NTOT];
__device__ int   g_bsum[SCANB];
__device__ __half g_hf[NNODES * FEAT];    // fp16 H (gather source for aggregate)
__device__ float g_x2[NNODES * FEAT];     // layer-1 output (fp32)
__device__ float g_as[NNODES * NHEADS];
__device__ float g_ad[NNODES * NHEADS];
// W split to bf16 hi/lo and transposed to [n][k] (B^T row-major), per layer
__device__ __nv_bfloat16 g_wt_hi[2][128 * 128];
__device__ __nv_bfloat16 g_wt_lo[2][128 * 128];

// ================= prep: W split/transpose (both layers) + zero counts =====
__global__ void k_prep(const float* __restrict__ W1, const float* __restrict__ W2, int n) {
    int i = blockIdx.x * blockDim.x + threadIdx.x;   // 65536 threads
    if (i < n) g_count[i] = 0;
    if (i < 128 * 128) {
        int k = i >> 7, nn = i & 127;          // W[k][nn]
        float w = W1[i];
        __nv_bfloat16 hi = __float2bfloat16(w);
        __nv_bfloat16 lo = __float2bfloat16(w - __bfloat162float(hi));
        g_wt_hi[0][nn * 128 + k] = hi;         // [n][k]
        g_wt_lo[0][nn * 128 + k] = lo;
        w = W2[i];
        hi = __float2bfloat16(w);
        lo = __float2bfloat16(w - __bfloat162float(hi));
        g_wt_hi[1][nn * 128 + k] = hi;
        g_wt_lo[1][nn * 128 + k] = lo;
    }
}

// ================= CSR build ===============================================
__global__ void k_hist(const int* __restrict__ dst, int e, int n) {
    int i = blockIdx.x * blockDim.x + threadIdx.x;
    int tot = e + n;
    if (i >= tot) return;
    int d = (i < e) ? dst[i] : (i - e);   // self-loops appended
    g_rank[i] = atomicAdd(&g_count[d], 1);
}

// stage 1: per-block (1024 elems) sums
__global__ void k_bsum(int n) {
    __shared__ int ws[32];
    int tid = threadIdx.x, lane = tid & 31, wid = tid >> 5;
    int i = blockIdx.x * 1024 + tid;
    int v = (i < n) ? g_count[i] : 0;
    #pragma unroll
    for (int off = 16; off >= 1; off >>= 1)
        v += __shfl_xor_sync(0xffffffffu, v, off);
    if (lane == 0) ws[wid] = v;
    __syncthreads();
    if (wid == 0) {
        int s = ws[lane];
        #pragma unroll
        for (int off = 16; off >= 1; off >>= 1)
            s += __shfl_xor_sync(0xffffffffu, s, off);
        if (lane == 0) g_bsum[blockIdx.x] = s;
    }
}

// stage 2: per-block scan; block offset computed in-kernel from g_bsum
__global__ void k_scanf(int nb, int n) {
    __shared__ int ws[32];
    __shared__ int sboff, stot;
    int tid = threadIdx.x, lane = tid & 31, wid = tid >> 5;
    if (tid == 0) { sboff = 0; stot = 0; }
    __syncthreads();
    if (tid < SCANB && tid < nb) {
        int b = g_bsum[tid];
        if (tid < blockIdx.x) atomicAdd(&sboff, b);
        atomicAdd(&stot, b);
    }
    int i = blockIdx.x * 1024 + tid;
    int v = (i < n) ? g_count[i] : 0;
    int x = v;
    #pragma unroll
    for (int off = 1; off < 32; off <<= 1) {
        int u = __shfl_up_sync(0xffffffffu, x, off);
        if (lane >= off) x += u;
    }
    if (lane == 31) ws[wid] = x;
    __syncthreads();
    if (wid == 0) {
        int w = ws[lane];
        #pragma unroll
        for (int off = 1; off < 32; off <<= 1) {
            int u = __shfl_up_sync(0xffffffffu, w, off);
            if (lane >= off) w += u;
        }
        ws[lane] = w;
    }
    __syncthreads();
    int prefix = (wid > 0) ? ws[wid - 1] : 0;
    if (i < n) g_rowptr[i] = sboff + prefix + x - v;
    if (blockIdx.x == 0 && tid == 0) g_rowptr[n] = stot;
}

__global__ void k_scatter(const int* __restrict__ src, const int* __restrict__ dst,
                          int e, int n) {
    int i = blockIdx.x * blockDim.x + threadIdx.x;
    int tot = e + n;
    if (i >= tot) return;
    int s, d;
    if (i < e) { s = src[i]; d = dst[i]; }
    else       { s = i - e;  d = i - e;  }
    g_ssrc[g_rowptr[d] + g_rank[i]] = s;
}

// ================= mma.sync bf16-split GEMM + fused alpha =================
// Hf16[128-row tile, 128] = X @ W.  256 threads (8 warps), warp owns 16 rows.
// 3-pass split: hi*hi + hi*lo + lo*hi (error ~1e-5), fp32 accumulators.
#define SXW 136                    // bf16 stride (=68 words -> bank-stride 4)
#define SM_XH 0
#define SM_XL (128 * SXW * 2)
#define SM_WH (2 * 128 * SXW * 2)
#define SM_WL (SM_WH + 128 * SXW * 2)
#define GEMM_SMEM (SM_WL + 128 * SXW * 2)   // 139264 B

__device__ __forceinline__ void mma16816(float* d, uint32_t a0, uint32_t a1,
                                         uint32_t a2, uint32_t a3,
                                         uint32_t b0, uint32_t b1) {
    asm volatile(
        "mma.sync.aligned.m16n8k16.row.col.f32.bf16.bf16.f32 "
        "{%0,%1,%2,%3}, {%4,%5,%6,%7}, {%8,%9}, {%0,%1,%2,%3};"
        : "+f"(d[0]), "+f"(d[1]), "+f"(d[2]), "+f"(d[3])
        : "r"(a0), "r"(a1), "r"(a2), "r"(a3), "r"(b0), "r"(b1));
}

__global__ void __launch_bounds__(256, 1)
k_gemm_hmma(const float* __restrict__ X,
            const __nv_bfloat16* __restrict__ wth, const __nv_bfloat16* __restrict__ wtl,
            __half* __restrict__ Hf,
            const float* __restrict__ asrc, const float* __restrict__ adst, int n) {
    extern __shared__ unsigned char sm[];
    __nv_bfloat16* sXh = (__nv_bfloat16*)(sm + SM_XH);
    __nv_bfloat16* sXl = (__nv_bfloat16*)(sm + SM_XL);
    __nv_bfloat16* sWh = (__nv_bfloat16*)(sm + SM_WH);
    __nv_bfloat16* sWl = (__nv_bfloat16*)(sm + SM_WL);
    __shared__ float sA[128], sB[128];

    int tid = threadIdx.x, lane = tid & 31, warp = tid >> 5;
    if (tid < 128) { sA[tid] = asrc[tid]; sB[tid] = adst[tid]; }

    // W tiles: copy prebuilt [n][k] bf16 into padded smem (16B chunks)
    for (int i = tid; i < 128 * 16; i += 256) {
        int r = i >> 4, c = i & 15;                   // c: 16B chunk (8 bf16)
        *(uint4*)&sWh[r * SXW + c * 8] = ((const uint4*)wth)[i];
        *(uint4*)&sWl[r * SXW + c * 8] = ((const uint4*)wtl)[i];
    }
    // X tile: load fp32, split to bf16 hi/lo
    int rbase = blockIdx.x * 128;
    for (int i = tid * 4; i < 128 * 128; i += 1024) {
        int r = i >> 7, k = i & 127;
        float4 v = make_float4(0.f, 0.f, 0.f, 0.f);
        int gr = rbase + r;
        if (gr < n) v = *(const float4*)&X[(size_t)gr * FEAT + k];
        __nv_bfloat16 h0 = __float2bfloat16(v.x), h1 = __float2bfloat16(v.y);
        __nv_bfloat16 h2 = __float2bfloat16(v.z), h3 = __float2bfloat16(v.w);
        __nv_bfloat16 l0 = __float2bfloat16(v.x - __bfloat162float(h0));
        __nv_bfloat16 l1 = __float2bfloat16(v.y - __bfloat162float(h1));
        __nv_bfloat16 l2 = __float2bfloat16(v.z - __bfloat162float(h2));
        __nv_bfloat16 l3 = __float2bfloat16(v.w - __bfloat162float(h3));
        __nv_bfloat16* ph = &sXh[r * SXW + k];
        __nv_bfloat16* pl = &sXl[r * SXW + k];
        ph[0] = h0; ph[1] = h1; ph[2] = h2; ph[3] = h3;
        pl[0] = l0; pl[1] = l1; pl[2] = l2; pl[3] = l3;
    }
    __syncthreads();

    int g  = lane >> 2;          // 0..7
    int qk = (lane & 3) * 2;     // k offset within fragment
    int rowA = warp * 16 + g;

    float d[16][4];
    #pragma unroll
    for (int t = 0; t < 16; t++)
        #pragma unroll
        for (int j = 0; j < 4; j++) d[t][j] = 0.f;

    const __nv_bfloat16* pxh0 = &sXh[rowA * SXW];
    const __nv_bfloat16* pxh8 = &sXh[(rowA + 8) * SXW];
    const __nv_bfloat16* pxl0 = &sXl[rowA * SXW];
    const __nv_bfloat16* pxl8 = &sXl[(rowA + 8) * SXW];

    #pragma unroll
    for (int ks = 0; ks < 8; ks++) {
        int k0 = ks * 16 + qk;
        uint32_t ah0 = *(const uint32_t*)&pxh0[k0];
        uint32_t ah1 = *(const uint32_t*)&pxh8[k0];
        uint32_t ah2 = *(const uint32_t*)&pxh0[k0 + 8];
        uint32_t ah3 = *(const uint32_t*)&pxh8[k0 + 8];
        uint32_t al0 = *(const uint32_t*)&pxl0[k0];
        uint32_t al1 = *(const uint32_t*)&pxl8[k0];
        uint32_t al2 = *(const uint32_t*)&pxl0[k0 + 8];
        uint32_t al3 = *(const uint32_t*)&pxl8[k0 + 8];
        #pragma unroll
        for (int nt = 0; nt < 16; nt++) {
            const __nv_bfloat16* pwh = &sWh[(nt * 8 + g) * SXW + k0];
            const __nv_bfloat16* pwl = &sWl[(nt * 8 + g) * SXW + k0];
            uint32_t bh0 = *(const uint32_t*)&pwh[0];
            uint32_t bh1 = *(const uint32_t*)&pwh[8];
            uint32_t bl0 = *(const uint32_t*)&pwl[0];
            uint32_t bl1 = *(const uint32_t*)&pwl[8];
            mma16816(d[nt], ah0, ah1, ah2, ah3, bh0, bh1);
            mma16816(d[nt], ah0, ah1, ah2, ah3, bl0, bl1);
            mma16816(d[nt], al0, al1, al2, al3, bh0, bh1);
        }
    }

    // ---- store H (fp16) + fused alpha dot-products (fp32) ----
    int r0g = rbase + warp * 16 + g;
    int r1g = r0g + 8;
    bool v0 = r0g < n, v1 = r1g < n;

    #pragma unroll
    for (int nt = 0; nt < 16; nt++) {
        int n0 = nt * 8 + qk;
        if (v0) *(__half2*)&Hf[(size_t)r0g * FEAT + n0] = __floats2half2_rn(d[nt][0], d[nt][1]);
        if (v1) *(__half2*)&Hf[(size_t)r1g * FEAT + n0] = __floats2half2_rn(d[nt][2], d[nt][3]);
    }

    #pragma unroll
    for (int h = 0; h < NHEADS; h++) {
        int nA = 2 * h * 8 + qk, nB = (2 * h + 1) * 8 + qk;
        float aA0 = sA[nA], aA1 = sA[nA + 1], aB0 = sA[nB], aB1 = sA[nB + 1];
        float dA0 = sB[nA], dA1 = sB[nA + 1], dB0 = sB[nB], dB1 = sB[nB + 1];
        float ps0 = d[2*h][0] * aA0 + d[2*h][1] * aA1 + d[2*h+1][0] * aB0 + d[2*h+1][1] * aB1;
        float pd0 = d[2*h][0] * dA0 + d[2*h][1] * dA1 + d[2*h+1][0] * dB0 + d[2*h+1][1] * dB1;
        float ps1 = d[2*h][2] * aA0 + d[2*h][3] * aA1 + d[2*h+1][2] * aB0 + d[2*h+1][3] * aB1;
        float pd1 = d[2*h][2] * dA0 + d[2*h][3] * dA1 + d[2*h+1][2] * dB0 + d[2*h+1][3] * dB1;
        ps0 += __shfl_xor_sync(0xffffffffu, ps0, 1);
        ps0 += __shfl_xor_sync(0xffffffffu, ps0, 2);
        pd0 += __shfl_xor_sync(0xffffffffu, pd0, 1);
        pd0 += __shfl_xor_sync(0xffffffffu, pd0, 2);
        ps1 += __shfl_xor_sync(0xffffffffu, ps1, 1);
        ps1 += __shfl_xor_sync(0xffffffffu, ps1, 2);
        pd1 += __shfl_xor_sync(0xffffffffu, pd1, 1);
        pd1 += __shfl_xor_sync(0xffffffffu, pd1, 2);
        if ((lane & 3) == 0) {
            if (v0) { g_as[r0g * NHEADS + h] = ps0; g_ad[r0g * NHEADS + h] = pd0; }
            if (v1) { g_as[r1g * NHEADS + h] = ps1; g_ad[r1g * NHEADS + h] = pd1; }
        }
    }
}

// ================= aggregation (fp16 H gather, fp32 math) =================
__global__ void k_aggregate(const __half* __restrict__ Hf, const float* __restrict__ bias,
                            float* __restrict__ out, int n) {
    int gw = (blockIdx.x * blockDim.x + threadIdx.x) >> 5;
    int lane = threadIdx.x & 31;
    if (gw >= n) return;
    int beg = g_rowptr[gw], end = g_rowptr[gw + 1];

    int head = lane >> 2;
    float adh = __ldg(&g_ad[gw * NHEADS + head]);

    float a0 = 0.f, a1 = 0.f, a2 = 0.f, a3 = 0.f, ssum = 0.f;

    int slot = lane & 3;
    int myj = beg + slot;
    int sj = (myj < end) ? __ldg(&g_ssrc[myj]) : 0;

    int j = beg;
    int jfull = beg + ((end - beg) & ~3);
    for (; j < jfull; j += 4) {
        int nx = j + 4 + slot;
        int sj_next = (nx < end) ? __ldg(&g_ssrc[nx]) : 0;
        #pragma unroll
        for (int t = 0; t < 4; t++) {
            int s = __shfl_sync(0xffffffffu, sj, t);
            float e = __ldg(&g_as[s * NHEADS + head]) + adh;
            e = (e > 0.f) ? e : 0.2f * e;
            float w = __expf(e);
            uint2 hv = *(const uint2*)&Hf[(size_t)s * FEAT + lane * 4];
            float2 f0 = __half22float2(*(__half2*)&hv.x);
            float2 f1 = __half22float2(*(__half2*)&hv.y);
            a0 += w * f0.x; a1 += w * f0.y; a2 += w * f1.x; a3 += w * f1.y;
            ssum += w;
        }
        sj = sj_next;
    }
    int rem = end - j;
    for (int t = 0; t < rem; t++) {
        int s = __shfl_sync(0xffffffffu, sj, t);
        float e = __ldg(&g_as[s * NHEADS + head]) + adh;
        e = (e > 0.f) ? e : 0.2f * e;
        float w = __expf(e);
        uint2 hv = *(const uint2*)&Hf[(size_t)s * FEAT + lane * 4];
        float2 f0 = __half22float2(*(__half2*)&hv.x);
        float2 f1 = __half22float2(*(__half2*)&hv.y);
        a0 += w * f0.x; a1 += w * f0.y; a2 += w * f1.x; a3 += w * f1.y;
        ssum += w;
    }

    float inv = 1.0f / (ssum + 1e-16f);
    float4 b = *(const float4*)&bias[lane * 4];
    float o0 = a0 * inv + b.x;
    float o1 = a1 * inv + b.y;
    float o2 = a2 * inv + b.z;
    float o3 = a3 * inv + b.w;
    o0 = (o0 > 0.f) ? o0 : (__expf(o0) - 1.f);
    o1 = (o1 > 0.f) ? o1 : (__expf(o1) - 1.f);
    o2 = (o2 > 0.f) ? o2 : (__expf(o2) - 1.f);
    o3 = (o3 > 0.f) ? o3 : (__expf(o3) - 1.f);
    *(float4*)&out[(size_t)gw * FEAT + lane * 4] = make_float4(o0, o1, o2, o3);
}

// ==========================================================================
extern "C" void kernel_launch(void* const* d_in, const int* in_sizes, int n_in,
                              void* d_out, int out_size) {
    const float* x   = (const float*)d_in[0];
    const int*   ei  = (const int*)  d_in[1];
    const float* W1  = (const float*)d_in[2];
    const float* as1 = (const float*)d_in[3];
    const float* ad1 = (const float*)d_in[4];
    const float* b1  = (const float*)d_in[5];
    const float* W2  = (const float*)d_in[6];
    const float* as2 = (const float*)d_in[7];
    const float* ad2 = (const float*)d_in[8];
    const float* b2  = (const float*)d_in[9];
    float* out = (float*)d_out;

    int n = in_sizes[0] / FEAT;   // 50000
    int e = in_sizes[1] / 2;      // 800000
    const int* src = ei;
    const int* dst = ei + e;
    int tot = e + n;
    int nb = (n + 1023) / 1024;   // scan blocks (49)

    float *p_x2;
    __half *p_hf;
    __nv_bfloat16 *p_wth, *p_wtl;
    cudaGetSymbolAddress((void**)&p_hf, g_hf);
    cudaGetSymbolAddress((void**)&p_x2, g_x2);
    cudaGetSymbolAddress((void**)&p_wth, g_wt_hi);
    cudaGetSymbolAddress((void**)&p_wtl, g_wt_lo);
    cudaFuncSetAttribute(k_gemm_hmma, cudaFuncAttributeMaxDynamicSharedMemorySize, GEMM_SMEM);

    int gtiles = (n + 127) / 128;

    // side stream + fork/join events (created once; creation is not device alloc)
    static cudaStream_t s_csr = nullptr;
    static cudaEvent_t ev_fork = nullptr, ev_join = nullptr;
    static bool overlap_ok = false;
    if (s_csr == nullptr) {
        overlap_ok =
            (cudaStreamCreateWithFlags(&s_csr, cudaStreamNonBlocking) == cudaSuccess) &&
            (cudaEventCreateWithFlags(&ev_fork, cudaEventDisableTiming) == cudaSuccess) &&
            (cudaEventCreateWithFlags(&ev_join, cudaEventDisableTiming) == cudaSuccess);
    }
    cudaStream_t sc = overlap_ok ? s_csr : (cudaStream_t)0;

    // (1) prep: W split both layers + zero counts (main/legacy stream)
    k_prep<<<256, 256>>>(W1, W2, n);

    // fork: CSR chain on side stream, concurrent with layer-1 GEMM
    if (overlap_ok) {
        cudaEventRecord(ev_fork, 0);
        cudaStreamWaitEvent(sc, ev_fork, 0);
    }
    k_hist   <<<(tot + 255) / 256, 256, 0, sc>>>(dst, e, n);
    k_bsum   <<<nb, 1024, 0, sc>>>(n);
    k_scanf  <<<nb, 1024, 0, sc>>>(nb, n);
    k_scatter<<<(tot + 255) / 256, 256, 0, sc>>>(src, dst, e, n);
    if (overlap_ok) cudaEventRecord(ev_join, sc);

    // layer-1 GEMM on main stream (independent of CSR)
    k_gemm_hmma<<<gtiles, 256, GEMM_SMEM>>>(x, p_wth, p_wtl, p_hf, as1, ad1, n);

    // join: aggregate needs both CSR and GEMM-1
    if (overlap_ok) cudaStreamWaitEvent(0, ev_join, 0);
    k_aggregate<<<(n + 7) / 8, 256>>>(p_hf, b1, p_x2, n);

    // layer 2 (serial chain)
    k_gemm_hmma<<<gtiles, 256, GEMM_SMEM>>>(p_x2, p_wth + 128 * 128, p_wtl + 128 * 128,
                                            p_hf, as2, ad2, n);
    k_aggregate<<<(n + 7) / 8, 256>>>(p_hf, b2, out, n);
}

// round 13
// speedup vs baseline: 1.4739x; 1.1089x over previous
#include <cuda_runtime.h>
#include <cuda_bf16.h>
#include <cuda_fp16.h>
#include <math.h>
#include <stdint.h>

#define NNODES 50000
#define NEDGES 800000
#define NTOT   (NNODES + NEDGES)
#define FEAT 128
#define NHEADS 8
#define SCANB 64          // max scan blocks (50000/1024 -> 49)

// ---- device scratch (no runtime allocation allowed) ----
__device__ int   g_count[NNODES];
__device__ int   g_rowptr[NNODES + 1];
__device__ int   g_rank[NTOT];
__device__ int   g_ssrc[NTOT];
__device__ int   g_bsum[SCANB];
__device__ __half g_hf[NNODES * FEAT];    // fp16 H (gather source for aggregate)
__device__ float g_x2[NNODES * FEAT];     // layer-1 output (fp32)
__device__ float g_as[NNODES * NHEADS];
__device__ float g_ad[NNODES * NHEADS];
// W split to bf16 hi/lo and transposed to [n][k] (B^T row-major), per layer
__device__ __nv_bfloat16 g_wt_hi[2][128 * 128];
__device__ __nv_bfloat16 g_wt_lo[2][128 * 128];

// ================= prep: W split/transpose (both layers) + zero counts =====
__global__ void k_prep(const float* __restrict__ W1, const float* __restrict__ W2, int n) {
    int i = blockIdx.x * blockDim.x + threadIdx.x;   // 65536 threads
    if (i < n) g_count[i] = 0;
    if (i < 128 * 128) {
        int k = i >> 7, nn = i & 127;          // W[k][nn]
        float w = W1[i];
        __nv_bfloat16 hi = __float2bfloat16(w);
        __nv_bfloat16 lo = __float2bfloat16(w - __bfloat162float(hi));
        g_wt_hi[0][nn * 128 + k] = hi;         // [n][k]
        g_wt_lo[0][nn * 128 + k] = lo;
        w = W2[i];
        hi = __float2bfloat16(w);
        lo = __float2bfloat16(w - __bfloat162float(hi));
        g_wt_hi[1][nn * 128 + k] = hi;
        g_wt_lo[1][nn * 128 + k] = lo;
    }
}

// ================= CSR build ===============================================
__global__ void k_hist(const int* __restrict__ dst, int e, int n) {
    int i = blockIdx.x * blockDim.x + threadIdx.x;
    int tot = e + n;
    if (i >= tot) return;
    int d = (i < e) ? dst[i] : (i - e);   // self-loops appended
    g_rank[i] = atomicAdd(&g_count[d], 1);
}

// stage 1: per-block (1024 elems) sums
__global__ void k_bsum(int n) {
    __shared__ int ws[32];
    int tid = threadIdx.x, lane = tid & 31, wid = tid >> 5;
    int i = blockIdx.x * 1024 + tid;
    int v = (i < n) ? g_count[i] : 0;
    #pragma unroll
    for (int off = 16; off >= 1; off >>= 1)
        v += __shfl_xor_sync(0xffffffffu, v, off);
    if (lane == 0) ws[wid] = v;
    __syncthreads();
    if (wid == 0) {
        int s = ws[lane];
        #pragma unroll
        for (int off = 16; off >= 1; off >>= 1)
            s += __shfl_xor_sync(0xffffffffu, s, off);
        if (lane == 0) g_bsum[blockIdx.x] = s;
    }
}

// stage 2: per-block scan; block offset computed in-kernel from g_bsum
__global__ void k_scanf(int nb, int n) {
    __shared__ int ws[32];
    __shared__ int sboff, stot;
    int tid = threadIdx.x, lane = tid & 31, wid = tid >> 5;
    if (tid == 0) { sboff = 0; stot = 0; }
    __syncthreads();
    if (tid < SCANB && tid < nb) {
        int b = g_bsum[tid];
        if (tid < blockIdx.x) atomicAdd(&sboff, b);
        atomicAdd(&stot, b);
    }
    int i = blockIdx.x * 1024 + tid;
    int v = (i < n) ? g_count[i] : 0;
    int x = v;
    #pragma unroll
    for (int off = 1; off < 32; off <<= 1) {
        int u = __shfl_up_sync(0xffffffffu, x, off);
        if (lane >= off) x += u;
    }
    if (lane == 31) ws[wid] = x;
    __syncthreads();
    if (wid == 0) {
        int w = ws[lane];
        #pragma unroll
        for (int off = 1; off < 32; off <<= 1) {
            int u = __shfl_up_sync(0xffffffffu, w, off);
            if (lane >= off) w += u;
        }
        ws[lane] = w;
    }
    __syncthreads();
    int prefix = (wid > 0) ? ws[wid - 1] : 0;
    if (i < n) g_rowptr[i] = sboff + prefix + x - v;
    if (blockIdx.x == 0 && tid == 0) g_rowptr[n] = stot;
}

__global__ void k_scatter(const int* __restrict__ src, const int* __restrict__ dst,
                          int e, int n) {
    int i = blockIdx.x * blockDim.x + threadIdx.x;
    int tot = e + n;
    if (i >= tot) return;
    int s, d;
    if (i < e) { s = src[i]; d = dst[i]; }
    else       { s = i - e;  d = i - e;  }
    g_ssrc[g_rowptr[d] + g_rank[i]] = s;
}

// ================= mma.sync bf16-split GEMM + fused alpha =================
// Hf16[64-row tile, 128] = X @ W.  256 threads (8 warps):
// warp = rowgroup (w>>1, 16 rows) x n-half (w&1, 64 cols).
// Per warp: 8 n-tiles x 8 ks x 3 passes = 192 MMA, d[8][4] accumulators.
// smem 104.4KB -> 2 blocks/SM -> 4 warps/SMSP (latency hiding).
#define SXW 136                    // bf16 stride (=68 words -> bank-stride 4)
#define SM_XH 0
#define SM_XL (64 * SXW * 2)
#define SM_WH (2 * 64 * SXW * 2)
#define SM_WL (SM_WH + 128 * SXW * 2)
#define GEMM_SMEM (SM_WL + 128 * SXW * 2)   // 104448 B

__device__ __forceinline__ void mma16816(float* d, uint32_t a0, uint32_t a1,
                                         uint32_t a2, uint32_t a3,
                                         uint32_t b0, uint32_t b1) {
    asm volatile(
        "mma.sync.aligned.m16n8k16.row.col.f32.bf16.bf16.f32 "
        "{%0,%1,%2,%3}, {%4,%5,%6,%7}, {%8,%9}, {%0,%1,%2,%3};"
        : "+f"(d[0]), "+f"(d[1]), "+f"(d[2]), "+f"(d[3])
        : "r"(a0), "r"(a1), "r"(a2), "r"(a3), "r"(b0), "r"(b1));
}

__global__ void __launch_bounds__(256, 2)
k_gemm_hmma(const float* __restrict__ X,
            const __nv_bfloat16* __restrict__ wth, const __nv_bfloat16* __restrict__ wtl,
            __half* __restrict__ Hf,
            const float* __restrict__ asrc, const float* __restrict__ adst, int n) {
    extern __shared__ unsigned char sm[];
    __nv_bfloat16* sXh = (__nv_bfloat16*)(sm + SM_XH);
    __nv_bfloat16* sXl = (__nv_bfloat16*)(sm + SM_XL);
    __nv_bfloat16* sWh = (__nv_bfloat16*)(sm + SM_WH);
    __nv_bfloat16* sWl = (__nv_bfloat16*)(sm + SM_WL);
    __shared__ float sA[128], sB[128];

    int tid = threadIdx.x, lane = tid & 31, warp = tid >> 5;
    if (tid < 128) { sA[tid] = asrc[tid]; sB[tid] = adst[tid]; }

    // W tiles: copy prebuilt [n][k] bf16 into padded smem (16B chunks)
    for (int i = tid; i < 128 * 16; i += 256) {
        int r = i >> 4, c = i & 15;                   // c: 16B chunk (8 bf16)
        *(uint4*)&sWh[r * SXW + c * 8] = ((const uint4*)wth)[i];
        *(uint4*)&sWl[r * SXW + c * 8] = ((const uint4*)wtl)[i];
    }
    // X tile (64 rows): load fp32, split to bf16 hi/lo
    int rbase = blockIdx.x * 64;
    for (int i = tid * 4; i < 64 * 128; i += 1024) {
        int r = i >> 7, k = i & 127;
        float4 v = make_float4(0.f, 0.f, 0.f, 0.f);
        int gr = rbase + r;
        if (gr < n) v = *(const float4*)&X[(size_t)gr * FEAT + k];
        __nv_bfloat16 h0 = __float2bfloat16(v.x), h1 = __float2bfloat16(v.y);
        __nv_bfloat16 h2 = __float2bfloat16(v.z), h3 = __float2bfloat16(v.w);
        __nv_bfloat16 l0 = __float2bfloat16(v.x - __bfloat162float(h0));
        __nv_bfloat16 l1 = __float2bfloat16(v.y - __bfloat162float(h1));
        __nv_bfloat16 l2 = __float2bfloat16(v.z - __bfloat162float(h2));
        __nv_bfloat16 l3 = __float2bfloat16(v.w - __bfloat162float(h3));
        __nv_bfloat16* ph = &sXh[r * SXW + k];
        __nv_bfloat16* pl = &sXl[r * SXW + k];
        ph[0] = h0; ph[1] = h1; ph[2] = h2; ph[3] = h3;
        pl[0] = l0; pl[1] = l1; pl[2] = l2; pl[3] = l3;
    }
    __syncthreads();

    int g  = lane >> 2;          // 0..7
    int qk = (lane & 3) * 2;     // k offset within fragment
    int half = warp & 1;         // n-half: cols half*64 .. half*64+63
    int rg   = warp >> 1;        // rowgroup: rows rg*16 .. rg*16+15
    int rowA = rg * 16 + g;
    int nbase = half * 64;

    float d[8][4];
    #pragma unroll
    for (int t = 0; t < 8; t++)
        #pragma unroll
        for (int j = 0; j < 4; j++) d[t][j] = 0.f;

    const __nv_bfloat16* pxh0 = &sXh[rowA * SXW];
    const __nv_bfloat16* pxh8 = &sXh[(rowA + 8) * SXW];
    const __nv_bfloat16* pxl0 = &sXl[rowA * SXW];
    const __nv_bfloat16* pxl8 = &sXl[(rowA + 8) * SXW];

    #pragma unroll
    for (int ks = 0; ks < 8; ks++) {
        int k0 = ks * 16 + qk;
        uint32_t ah0 = *(const uint32_t*)&pxh0[k0];
        uint32_t ah1 = *(const uint32_t*)&pxh8[k0];
        uint32_t ah2 = *(const uint32_t*)&pxh0[k0 + 8];
        uint32_t ah3 = *(const uint32_t*)&pxh8[k0 + 8];
        uint32_t al0 = *(const uint32_t*)&pxl0[k0];
        uint32_t al1 = *(const uint32_t*)&pxl8[k0];
        uint32_t al2 = *(const uint32_t*)&pxl0[k0 + 8];
        uint32_t al3 = *(const uint32_t*)&pxl8[k0 + 8];
        #pragma unroll
        for (int nt = 0; nt < 8; nt++) {
            const __nv_bfloat16* pwh = &sWh[(nbase + nt * 8 + g) * SXW + k0];
            const __nv_bfloat16* pwl = &sWl[(nbase + nt * 8 + g) * SXW + k0];
            uint32_t bh0 = *(const uint32_t*)&pwh[0];
            uint32_t bh1 = *(const uint32_t*)&pwh[8];
            uint32_t bl0 = *(const uint32_t*)&pwl[0];
            uint32_t bl1 = *(const uint32_t*)&pwl[8];
            mma16816(d[nt], ah0, ah1, ah2, ah3, bh0, bh1);
            mma16816(d[nt], ah0, ah1, ah2, ah3, bl0, bl1);
            mma16816(d[nt], al0, al1, al2, al3, bh0, bh1);
        }
    }

    // ---- store H (fp16) + fused alpha dot-products (fp32) ----
    int r0g = rbase + rowA;
    int r1g = r0g + 8;
    bool v0 = r0g < n, v1 = r1g < n;

    #pragma unroll
    for (int nt = 0; nt < 8; nt++) {
        int n0 = nbase + nt * 8 + qk;
        if (v0) *(__half2*)&Hf[(size_t)r0g * FEAT + n0] = __floats2half2_rn(d[nt][0], d[nt][1]);
        if (v1) *(__half2*)&Hf[(size_t)r1g * FEAT + n0] = __floats2half2_rn(d[nt][2], d[nt][3]);
    }

    // this warp's 64 cols = 4 heads (global head = half*4 + h)
    #pragma unroll
    for (int h = 0; h < 4; h++) {
        int gh = half * 4 + h;
        int nA = nbase + 2 * h * 8 + qk, nB = nbase + (2 * h + 1) * 8 + qk;
        float aA0 = sA[nA], aA1 = sA[nA + 1], aB0 = sA[nB], aB1 = sA[nB + 1];
        float dA0 = sB[nA], dA1 = sB[nA + 1], dB0 = sB[nB], dB1 = sB[nB + 1];
        float ps0 = d[2*h][0] * aA0 + d[2*h][1] * aA1 + d[2*h+1][0] * aB0 + d[2*h+1][1] * aB1;
        float pd0 = d[2*h][0] * dA0 + d[2*h][1] * dA1 + d[2*h+1][0] * dB0 + d[2*h+1][1] * dB1;
        float ps1 = d[2*h][2] * aA0 + d[2*h][3] * aA1 + d[2*h+1][2] * aB0 + d[2*h+1][3] * aB1;
        float pd1 = d[2*h][2] * dA0 + d[2*h][3] * dA1 + d[2*h+1][2] * dB0 + d[2*h+1][3] * dB1;
        ps0 += __shfl_xor_sync(0xffffffffu, ps0, 1);
        ps0 += __shfl_xor_sync(0xffffffffu, ps0, 2);
        pd0 += __shfl_xor_sync(0xffffffffu, pd0, 1);
        pd0 += __shfl_xor_sync(0xffffffffu, pd0, 2);
        ps1 += __shfl_xor_sync(0xffffffffu, ps1, 1);
        ps1 += __shfl_xor_sync(0xffffffffu, ps1, 2);
        pd1 += __shfl_xor_sync(0xffffffffu, pd1, 1);
        pd1 += __shfl_xor_sync(0xffffffffu, pd1, 2);
        if ((lane & 3) == 0) {
            if (v0) { g_as[r0g * NHEADS + gh] = ps0; g_ad[r0g * NHEADS + gh] = pd0; }
            if (v1) { g_as[r1g * NHEADS + gh] = ps1; g_ad[r1g * NHEADS + gh] = pd1; }
        }
    }
}

// ================= aggregation (fp16 H gather, chunk-8 prefetch) ==========
__global__ void k_aggregate(const __half* __restrict__ Hf, const float* __restrict__ bias,
                            float* __restrict__ out, int n) {
    int gw = (blockIdx.x * blockDim.x + threadIdx.x) >> 5;
    int lane = threadIdx.x & 31;
    if (gw >= n) return;
    int beg = g_rowptr[gw], end = g_rowptr[gw + 1];

    int head = lane >> 2;
    float adh = __ldg(&g_ad[gw * NHEADS + head]);

    float a0 = 0.f, a1 = 0.f, a2 = 0.f, a3 = 0.f, ssum = 0.f;

    int slot = lane & 7;          // 8 edge slots per chunk (MLP=8)
    int myj = beg + slot;
    int sj = (myj < end) ? __ldg(&g_ssrc[myj]) : 0;

    int j = beg;
    int jfull = beg + ((end - beg) & ~7);
    for (; j < jfull; j += 8) {
        int nx = j + 8 + slot;
        int sj_next = (nx < end) ? __ldg(&g_ssrc[nx]) : 0;
        #pragma unroll
        for (int t = 0; t < 8; t++) {
            int s = __shfl_sync(0xffffffffu, sj, t);
            float e = __ldg(&g_as[s * NHEADS + head]) + adh;
            e = (e > 0.f) ? e : 0.2f * e;
            float w = __expf(e);
            uint2 hv = *(const uint2*)&Hf[(size_t)s * FEAT + lane * 4];
            float2 f0 = __half22float2(*(__half2*)&hv.x);
            float2 f1 = __half22float2(*(__half2*)&hv.y);
            a0 += w * f0.x; a1 += w * f0.y; a2 += w * f1.x; a3 += w * f1.y;
            ssum += w;
        }
        sj = sj_next;
    }
    int rem = end - j;
    for (int t = 0; t < rem; t++) {
        int s = __shfl_sync(0xffffffffu, sj, t);
        float e = __ldg(&g_as[s * NHEADS + head]) + adh;
        e = (e > 0.f) ? e : 0.2f * e;
        float w = __expf(e);
        uint2 hv = *(const uint2*)&Hf[(size_t)s * FEAT + lane * 4];
        float2 f0 = __half22float2(*(__half2*)&hv.x);
        float2 f1 = __half22float2(*(__half2*)&hv.y);
        a0 += w * f0.x; a1 += w * f0.y; a2 += w * f1.x; a3 += w * f1.y;
        ssum += w;
    }

    float inv = 1.0f / (ssum + 1e-16f);
    float4 b = *(const float4*)&bias[lane * 4];
    float o0 = a0 * inv + b.x;
    float o1 = a1 * inv + b.y;
    float o2 = a2 * inv + b.z;
    float o3 = a3 * inv + b.w;
    o0 = (o0 > 0.f) ? o0 : (__expf(o0) - 1.f);
    o1 = (o1 > 0.f) ? o1 : (__expf(o1) - 1.f);
    o2 = (o2 > 0.f) ? o2 : (__expf(o2) - 1.f);
    o3 = (o3 > 0.f) ? o3 : (__expf(o3) - 1.f);
    *(float4*)&out[(size_t)gw * FEAT + lane * 4] = make_float4(o0, o1, o2, o3);
}

// ==========================================================================
extern "C" void kernel_launch(void* const* d_in, const int* in_sizes, int n_in,
                              void* d_out, int out_size) {
    const float* x   = (const float*)d_in[0];
    const int*   ei  = (const int*)  d_in[1];
    const float* W1  = (const float*)d_in[2];
    const float* as1 = (const float*)d_in[3];
    const float* ad1 = (const float*)d_in[4];
    const float* b1  = (const float*)d_in[5];
    const float* W2  = (const float*)d_in[6];
    const float* as2 = (const float*)d_in[7];
    const float* ad2 = (const float*)d_in[8];
    const float* b2  = (const float*)d_in[9];
    float* out = (float*)d_out;

    int n = in_sizes[0] / FEAT;   // 50000
    int e = in_sizes[1] / 2;      // 800000
    const int* src = ei;
    const int* dst = ei + e;
    int tot = e + n;
    int nb = (n + 1023) / 1024;   // scan blocks (49)

    float *p_x2;
    __half *p_hf;
    __nv_bfloat16 *p_wth, *p_wtl;
    cudaGetSymbolAddress((void**)&p_hf, g_hf);
    cudaGetSymbolAddress((void**)&p_x2, g_x2);
    cudaGetSymbolAddress((void**)&p_wth, g_wt_hi);
    cudaGetSymbolAddress((void**)&p_wtl, g_wt_lo);
    cudaFuncSetAttribute(k_gemm_hmma, cudaFuncAttributeMaxDynamicSharedMemorySize, GEMM_SMEM);

    int gtiles = (n + 63) / 64;

    // side stream + fork/join events (created once; creation is not device alloc)
    static cudaStream_t s_csr = nullptr;
    static cudaEvent_t ev_fork = nullptr, ev_join = nullptr;
    static bool overlap_ok = false;
    if (s_csr == nullptr) {
        overlap_ok =
            (cudaStreamCreateWithFlags(&s_csr, cudaStreamNonBlocking) == cudaSuccess) &&
            (cudaEventCreateWithFlags(&ev_fork, cudaEventDisableTiming) == cudaSuccess) &&
            (cudaEventCreateWithFlags(&ev_join, cudaEventDisableTiming) == cudaSuccess);
    }
    cudaStream_t sc = overlap_ok ? s_csr : (cudaStream_t)0;

    // (1) prep: W split both layers + zero counts (main/legacy stream)
    k_prep<<<256, 256>>>(W1, W2, n);

    // fork: CSR chain on side stream, concurrent with layer-1 GEMM
    if (overlap_ok) {
        cudaEventRecord(ev_fork, 0);
        cudaStreamWaitEvent(sc, ev_fork, 0);
    }
    k_hist   <<<(tot + 255) / 256, 256, 0, sc>>>(dst, e, n);
    k_bsum   <<<nb, 1024, 0, sc>>>(n);
    k_scanf  <<<nb, 1024, 0, sc>>>(nb, n);
    k_scatter<<<(tot + 255) / 256, 256, 0, sc>>>(src, dst, e, n);
    if (overlap_ok) cudaEventRecord(ev_join, sc);

    // layer-1 GEMM on main stream (independent of CSR)
    k_gemm_hmma<<<gtiles, 256, GEMM_SMEM>>>(x, p_wth, p_wtl, p_hf, as1, ad1, n);

    // join: aggregate needs both CSR and GEMM-1
    if (overlap_ok) cudaStreamWaitEvent(0, ev_join, 0);
    k_aggregate<<<(n + 7) / 8, 256>>>(p_hf, b1, p_x2, n);

    // layer 2 (serial chain)
    k_gemm_hmma<<<gtiles, 256, GEMM_SMEM>>>(p_x2, p_wth + 128 * 128, p_wtl + 128 * 128,
                                            p_hf, as2, ad2, n);
    k_aggregate<<<(n + 7) / 8, 256>>>(p_hf, b2, out, n);
}

// round 14
// speedup vs baseline: 1.6357x; 1.1098x over previous
#include <cuda_runtime.h>
#include <cuda_fp16.h>
#include <math.h>
#include <stdint.h>

#define NNODES 50000
#define NEDGES 800000
#define NTOT   (NNODES + NEDGES)
#define FEAT 128
#define NHEADS 8
#define SCANB 64          // max scan blocks (50000/1024 -> 49)

// ---- device scratch (no runtime allocation allowed) ----
__device__ int   g_count[NNODES];
__device__ int   g_rowptr[NNODES + 1];
__device__ int   g_rank[NTOT];
__device__ int   g_ssrc[NTOT];
__device__ int   g_bsum[SCANB];
__device__ __half g_hf[NNODES * FEAT];    // fp16 H (gather source for aggregate)
__device__ float g_x2[NNODES * FEAT];     // layer-1 output (fp32)
__device__ float g_as[NNODES * NHEADS];
__device__ float g_ad[NNODES * NHEADS];
// W as fp16, transposed to [n][k] (B^T row-major), per layer
__device__ __half g_wt[2][128 * 128];

// ================= prep: W transpose to fp16 (both layers) ================
__global__ void k_prepw(const float* __restrict__ W1, const float* __restrict__ W2) {
    int i = blockIdx.x * blockDim.x + threadIdx.x;
    if (i >= 128 * 128) return;
    int k = i >> 7, nn = i & 127;          // W[k][nn]
    g_wt[0][nn * 128 + k] = __float2half(W1[i]);   // [n][k]
    g_wt[1][nn * 128 + k] = __float2half(W2[i]);
}

__global__ void k_zero(int n) {
    int i = blockIdx.x * blockDim.x + threadIdx.x;
    if (i < n) g_count[i] = 0;
}

// ================= CSR build ===============================================
__global__ void k_hist(const int* __restrict__ dst, int e, int n) {
    int i = blockIdx.x * blockDim.x + threadIdx.x;
    int tot = e + n;
    if (i >= tot) return;
    int d = (i < e) ? dst[i] : (i - e);   // self-loops appended
    g_rank[i] = atomicAdd(&g_count[d], 1);
}

// stage 1: per-block (1024 elems) sums
__global__ void k_bsum(int n) {
    __shared__ int ws[32];
    int tid = threadIdx.x, lane = tid & 31, wid = tid >> 5;
    int i = blockIdx.x * 1024 + tid;
    int v = (i < n) ? g_count[i] : 0;
    #pragma unroll
    for (int off = 16; off >= 1; off >>= 1)
        v += __shfl_xor_sync(0xffffffffu, v, off);
    if (lane == 0) ws[wid] = v;
    __syncthreads();
    if (wid == 0) {
        int s = ws[lane];
        #pragma unroll
        for (int off = 16; off >= 1; off >>= 1)
            s += __shfl_xor_sync(0xffffffffu, s, off);
        if (lane == 0) g_bsum[blockIdx.x] = s;
    }
}

// stage 2: per-block scan; block offset computed in-kernel from g_bsum
__global__ void k_scanf(int nb, int n) {
    __shared__ int ws[32];
    __shared__ int sboff, stot;
    int tid = threadIdx.x, lane = tid & 31, wid = tid >> 5;
    if (tid == 0) { sboff = 0; stot = 0; }
    __syncthreads();
    if (tid < SCANB && tid < nb) {
        int b = g_bsum[tid];
        if (tid < blockIdx.x) atomicAdd(&sboff, b);
        atomicAdd(&stot, b);
    }
    int i = blockIdx.x * 1024 + tid;
    int v = (i < n) ? g_count[i] : 0;
    int x = v;
    #pragma unroll
    for (int off = 1; off < 32; off <<= 1) {
        int u = __shfl_up_sync(0xffffffffu, x, off);
        if (lane >= off) x += u;
    }
    if (lane == 31) ws[wid] = x;
    __syncthreads();
    if (wid == 0) {
        int w = ws[lane];
        #pragma unroll
        for (int off = 1; off < 32; off <<= 1) {
            int u = __shfl_up_sync(0xffffffffu, w, off);
            if (lane >= off) w += u;
        }
        ws[lane] = w;
    }
    __syncthreads();
    int prefix = (wid > 0) ? ws[wid - 1] : 0;
    if (i < n) g_rowptr[i] = sboff + prefix + x - v;
    if (blockIdx.x == 0 && tid == 0) g_rowptr[n] = stot;
}

__global__ void k_scatter(const int* __restrict__ src, const int* __restrict__ dst,
                          int e, int n) {
    int i = blockIdx.x * blockDim.x + threadIdx.x;
    int tot = e + n;
    if (i >= tot) return;
    int s, d;
    if (i < e) { s = src[i]; d = dst[i]; }
    else       { s = i - e;  d = i - e;  }
    g_ssrc[g_rowptr[d] + g_rank[i]] = s;
}

// ================= mma.sync fp16 2-pass-split GEMM + fused alpha ==========
// Hf16[64-row tile, 128] = X @ W.  256 threads (8 warps):
// warp = rowgroup (w>>1, 16 rows) x n-half (w&1, 64 cols).
// X split: x = xh + xl (fp16); W single fp16. H = xh*W + xl*W (fp32 accum).
// Dropped term x*(w - fp16(w)) -> ~1.5e-4 relative error.
// Per warp: 8 nt x 8 ks x 2 passes = 128 MMA, d[8][4] accumulators.
// smem 69.6KB -> 3 blocks/SM.
#define SXW 136                    // fp16 stride (=68 words -> bank-stride 4)
#define SM_XH 0
#define SM_XL (64 * SXW * 2)
#define SM_W  (2 * 64 * SXW * 2)
#define GEMM_SMEM (SM_W + 128 * SXW * 2)   // 69632 B

__device__ __forceinline__ void mma16816(float* d, uint32_t a0, uint32_t a1,
                                         uint32_t a2, uint32_t a3,
                                         uint32_t b0, uint32_t b1) {
    asm volatile(
        "mma.sync.aligned.m16n8k16.row.col.f32.f16.f16.f32 "
        "{%0,%1,%2,%3}, {%4,%5,%6,%7}, {%8,%9}, {%0,%1,%2,%3};"
        : "+f"(d[0]), "+f"(d[1]), "+f"(d[2]), "+f"(d[3])
        : "r"(a0), "r"(a1), "r"(a2), "r"(a3), "r"(b0), "r"(b1));
}

__global__ void __launch_bounds__(256, 3)
k_gemm_hmma(const float* __restrict__ X, const __half* __restrict__ wt,
            __half* __restrict__ Hf,
            const float* __restrict__ asrc, const float* __restrict__ adst, int n) {
    extern __shared__ unsigned char sm[];
    __half* sXh = (__half*)(sm + SM_XH);
    __half* sXl = (__half*)(sm + SM_XL);
    __half* sW  = (__half*)(sm + SM_W);
    __shared__ float sA[128], sB[128];

    int tid = threadIdx.x, lane = tid & 31, warp = tid >> 5;
    if (tid < 128) { sA[tid] = asrc[tid]; sB[tid] = adst[tid]; }

    // W tile: copy prebuilt [n][k] fp16 into padded smem (16B chunks)
    for (int i = tid; i < 128 * 16; i += 256) {
        int r = i >> 4, c = i & 15;                   // c: 16B chunk (8 fp16)
        *(uint4*)&sW[r * SXW + c * 8] = ((const uint4*)wt)[i];
    }
    // X tile (64 rows): load fp32, split to fp16 hi/lo
    int rbase = blockIdx.x * 64;
    for (int i = tid * 4; i < 64 * 128; i += 1024) {
        int r = i >> 7, k = i & 127;
        float4 v = make_float4(0.f, 0.f, 0.f, 0.f);
        int gr = rbase + r;
        if (gr < n) v = *(const float4*)&X[(size_t)gr * FEAT + k];
        __half h0 = __float2half(v.x), h1 = __float2half(v.y);
        __half h2 = __float2half(v.z), h3 = __float2half(v.w);
        __half l0 = __float2half(v.x - __half2float(h0));
        __half l1 = __float2half(v.y - __half2float(h1));
        __half l2 = __float2half(v.z - __half2float(h2));
        __half l3 = __float2half(v.w - __half2float(h3));
        __half* ph = &sXh[r * SXW + k];
        __half* pl = &sXl[r * SXW + k];
        ph[0] = h0; ph[1] = h1; ph[2] = h2; ph[3] = h3;
        pl[0] = l0; pl[1] = l1; pl[2] = l2; pl[3] = l3;
    }
    __syncthreads();

    int g  = lane >> 2;          // 0..7
    int qk = (lane & 3) * 2;     // k offset within fragment
    int half = warp & 1;         // n-half: cols half*64 .. half*64+63
    int rg   = warp >> 1;        // rowgroup: rows rg*16 .. rg*16+15
    int rowA = rg * 16 + g;
    int nbase = half * 64;

    float d[8][4];
    #pragma unroll
    for (int t = 0; t < 8; t++)
        #pragma unroll
        for (int j = 0; j < 4; j++) d[t][j] = 0.f;

    const __half* pxh0 = &sXh[rowA * SXW];
    const __half* pxh8 = &sXh[(rowA + 8) * SXW];
    const __half* pxl0 = &sXl[rowA * SXW];
    const __half* pxl8 = &sXl[(rowA + 8) * SXW];

    #pragma unroll
    for (int ks = 0; ks < 8; ks++) {
        int k0 = ks * 16 + qk;
        uint32_t ah0 = *(const uint32_t*)&pxh0[k0];
        uint32_t ah1 = *(const uint32_t*)&pxh8[k0];
        uint32_t ah2 = *(const uint32_t*)&pxh0[k0 + 8];
        uint32_t ah3 = *(const uint32_t*)&pxh8[k0 + 8];
        uint32_t al0 = *(const uint32_t*)&pxl0[k0];
        uint32_t al1 = *(const uint32_t*)&pxl8[k0];
        uint32_t al2 = *(const uint32_t*)&pxl0[k0 + 8];
        uint32_t al3 = *(const uint32_t*)&pxl8[k0 + 8];
        #pragma unroll
        for (int nt = 0; nt < 8; nt++) {
            const __half* pw = &sW[(nbase + nt * 8 + g) * SXW + k0];
            uint32_t b0 = *(const uint32_t*)&pw[0];
            uint32_t b1 = *(const uint32_t*)&pw[8];
            mma16816(d[nt], ah0, ah1, ah2, ah3, b0, b1);
            mma16816(d[nt], al0, al1, al2, al3, b0, b1);
        }
    }

    // ---- store H (fp16) + fused alpha dot-products (fp32) ----
    int r0g = rbase + rowA;
    int r1g = r0g + 8;
    bool v0 = r0g < n, v1 = r1g < n;

    #pragma unroll
    for (int nt = 0; nt < 8; nt++) {
        int n0 = nbase + nt * 8 + qk;
        if (v0) *(__half2*)&Hf[(size_t)r0g * FEAT + n0] = __floats2half2_rn(d[nt][0], d[nt][1]);
        if (v1) *(__half2*)&Hf[(size_t)r1g * FEAT + n0] = __floats2half2_rn(d[nt][2], d[nt][3]);
    }

    // this warp's 64 cols = 4 heads (global head = half*4 + h)
    #pragma unroll
    for (int h = 0; h < 4; h++) {
        int gh = half * 4 + h;
        int nA = nbase + 2 * h * 8 + qk, nB = nbase + (2 * h + 1) * 8 + qk;
        float aA0 = sA[nA], aA1 = sA[nA + 1], aB0 = sA[nB], aB1 = sA[nB + 1];
        float dA0 = sB[nA], dA1 = sB[nA + 1], dB0 = sB[nB], dB1 = sB[nB + 1];
        float ps0 = d[2*h][0] * aA0 + d[2*h][1] * aA1 + d[2*h+1][0] * aB0 + d[2*h+1][1] * aB1;
        float pd0 = d[2*h][0] * dA0 + d[2*h][1] * dA1 + d[2*h+1][0] * dB0 + d[2*h+1][1] * dB1;
        float ps1 = d[2*h][2] * aA0 + d[2*h][3] * aA1 + d[2*h+1][2] * aB0 + d[2*h+1][3] * aB1;
        float pd1 = d[2*h][2] * dA0 + d[2*h][3] * dA1 + d[2*h+1][2] * dB0 + d[2*h+1][3] * dB1;
        ps0 += __shfl_xor_sync(0xffffffffu, ps0, 1);
        ps0 += __shfl_xor_sync(0xffffffffu, ps0, 2);
        pd0 += __shfl_xor_sync(0xffffffffu, pd0, 1);
        pd0 += __shfl_xor_sync(0xffffffffu, pd0, 2);
        ps1 += __shfl_xor_sync(0xffffffffu, ps1, 1);
        ps1 += __shfl_xor_sync(0xffffffffu, ps1, 2);
        pd1 += __shfl_xor_sync(0xffffffffu, pd1, 1);
        pd1 += __shfl_xor_sync(0xffffffffu, pd1, 2);
        if ((lane & 3) == 0) {
            if (v0) { g_as[r0g * NHEADS + gh] = ps0; g_ad[r0g * NHEADS + gh] = pd0; }
            if (v1) { g_as[r1g * NHEADS + gh] = ps1; g_ad[r1g * NHEADS + gh] = pd1; }
        }
    }
}

// ================= aggregation (fp16 H gather, chunk-8 prefetch) ==========
__global__ void k_aggregate(const __half* __restrict__ Hf, const float* __restrict__ bias,
                            float* __restrict__ out, int n) {
    int gw = (blockIdx.x * blockDim.x + threadIdx.x) >> 5;
    int lane = threadIdx.x & 31;
    if (gw >= n) return;
    int beg = g_rowptr[gw], end = g_rowptr[gw + 1];

    int head = lane >> 2;
    float adh = __ldg(&g_ad[gw * NHEADS + head]);

    float a0 = 0.f, a1 = 0.f, a2 = 0.f, a3 = 0.f, ssum = 0.f;

    int slot = lane & 7;          // 8 edge slots per chunk (MLP=8)
    int myj = beg + slot;
    int sj = (myj < end) ? __ldg(&g_ssrc[myj]) : 0;

    int j = beg;
    int jfull = beg + ((end - beg) & ~7);
    for (; j < jfull; j += 8) {
        int nx = j + 8 + slot;
        int sj_next = (nx < end) ? __ldg(&g_ssrc[nx]) : 0;
        #pragma unroll
        for (int t = 0; t < 8; t++) {
            int s = __shfl_sync(0xffffffffu, sj, t);
            float e = __ldg(&g_as[s * NHEADS + head]) + adh;
            e = (e > 0.f) ? e : 0.2f * e;
            float w = __expf(e);
            uint2 hv = *(const uint2*)&Hf[(size_t)s * FEAT + lane * 4];
            float2 f0 = __half22float2(*(__half2*)&hv.x);
            float2 f1 = __half22float2(*(__half2*)&hv.y);
            a0 += w * f0.x; a1 += w * f0.y; a2 += w * f1.x; a3 += w * f1.y;
            ssum += w;
        }
        sj = sj_next;
    }
    int rem = end - j;
    for (int t = 0; t < rem; t++) {
        int s = __shfl_sync(0xffffffffu, sj, t);
        float e = __ldg(&g_as[s * NHEADS + head]) + adh;
        e = (e > 0.f) ? e : 0.2f * e;
        float w = __expf(e);
        uint2 hv = *(const uint2*)&Hf[(size_t)s * FEAT + lane * 4];
        float2 f0 = __half22float2(*(__half2*)&hv.x);
        float2 f1 = __half22float2(*(__half2*)&hv.y);
        a0 += w * f0.x; a1 += w * f0.y; a2 += w * f1.x; a3 += w * f1.y;
        ssum += w;
    }

    float inv = 1.0f / (ssum + 1e-16f);
    float4 b = *(const float4*)&bias[lane * 4];
    float o0 = a0 * inv + b.x;
    float o1 = a1 * inv + b.y;
    float o2 = a2 * inv + b.z;
    float o3 = a3 * inv + b.w;
    o0 = (o0 > 0.f) ? o0 : (__expf(o0) - 1.f);
    o1 = (o1 > 0.f) ? o1 : (__expf(o1) - 1.f);
    o2 = (o2 > 0.f) ? o2 : (__expf(o2) - 1.f);
    o3 = (o3 > 0.f) ? o3 : (__expf(o3) - 1.f);
    *(float4*)&out[(size_t)gw * FEAT + lane * 4] = make_float4(o0, o1, o2, o3);
}

// ==========================================================================
extern "C" void kernel_launch(void* const* d_in, const int* in_sizes, int n_in,
                              void* d_out, int out_size) {
    const float* x   = (const float*)d_in[0];
    const int*   ei  = (const int*)  d_in[1];
    const float* W1  = (const float*)d_in[2];
    const float* as1 = (const float*)d_in[3];
    const float* ad1 = (const float*)d_in[4];
    const float* b1  = (const float*)d_in[5];
    const float* W2  = (const float*)d_in[6];
    const float* as2 = (const float*)d_in[7];
    const float* ad2 = (const float*)d_in[8];
    const float* b2  = (const float*)d_in[9];
    float* out = (float*)d_out;

    int n = in_sizes[0] / FEAT;   // 50000
    int e = in_sizes[1] / 2;      // 800000
    const int* src = ei;
    const int* dst = ei + e;
    int tot = e + n;
    int nb = (n + 1023) / 1024;   // scan blocks (49)

    float *p_x2;
    __half *p_hf, *p_wt;
    cudaGetSymbolAddress((void**)&p_hf, g_hf);
    cudaGetSymbolAddress((void**)&p_x2, g_x2);
    cudaGetSymbolAddress((void**)&p_wt, g_wt);
    cudaFuncSetAttribute(k_gemm_hmma, cudaFuncAttributeMaxDynamicSharedMemorySize, GEMM_SMEM);

    int gtiles = (n + 63) / 64;

    // side stream + fork/join events (created once; creation is not device alloc)
    static cudaStream_t s_csr = nullptr;
    static cudaEvent_t ev_fork = nullptr, ev_join = nullptr;
    static bool overlap_ok = false;
    if (s_csr == nullptr) {
        overlap_ok =
            (cudaStreamCreateWithFlags(&s_csr, cudaStreamNonBlocking) == cudaSuccess) &&
            (cudaEventCreateWithFlags(&ev_fork, cudaEventDisableTiming) == cudaSuccess) &&
            (cudaEventCreateWithFlags(&ev_join, cudaEventDisableTiming) == cudaSuccess);
    }
    cudaStream_t sc = overlap_ok ? s_csr : (cudaStream_t)0;

    // fork immediately: CSR chain (zero->hist->scan->scatter) on side stream,
    // W-prep + layer-1 GEMM on main stream
    if (overlap_ok) {
        cudaEventRecord(ev_fork, 0);
        cudaStreamWaitEvent(sc, ev_fork, 0);
    }
    k_zero   <<<(n + 255) / 256, 256, 0, sc>>>(n);
    k_hist   <<<(tot + 255) / 256, 256, 0, sc>>>(dst, e, n);
    k_bsum   <<<nb, 1024, 0, sc>>>(n);
    k_scanf  <<<nb, 1024, 0, sc>>>(nb, n);
    k_scatter<<<(tot + 255) / 256, 256, 0, sc>>>(src, dst, e, n);
    if (overlap_ok) cudaEventRecord(ev_join, sc);

    // main stream: W prep + layer-1 GEMM (independent of CSR)
    k_prepw<<<64, 256>>>(W1, W2);
    k_gemm_hmma<<<gtiles, 256, GEMM_SMEM>>>(x, p_wt, p_hf, as1, ad1, n);

    // join: aggregate needs both CSR and GEMM-1
    if (overlap_ok) cudaStreamWaitEvent(0, ev_join, 0);
    k_aggregate<<<(n + 7) / 8, 256>>>(p_hf, b1, p_x2, n);

    // layer 2 (serial chain)
    k_gemm_hmma<<<gtiles, 256, GEMM_SMEM>>>(p_x2, p_wt + 128 * 128, p_hf, as2, ad2, n);
    k_aggregate<<<(n + 7) / 8, 256>>>(p_hf, b2, out, n);
}